// round 12
// baseline (speedup 1.0000x reference)
#include <cuda_runtime.h>
#include <cuda_bf16.h>
#include <cstdint>
#include <math.h>

// ---------------- problem constants ----------------
#define NB 2
#define NS 1024
#define ND 1024
#define NH 16
#define NDH 64
#define NL 4
#define NDFF 4096
#define NV 32000
#define NR 2047              // 2*MAXLEN-1
#define NROWS (NB*NS)        // 2048

// ---------------- scratch (static device allocations) ----------------
__device__ float g_x[NROWS*ND];
__device__ float g_qkv[NROWS*3*ND];                   // fused q|k|v, stride 3072
__device__ float g_p[2*NROWS*ND];                     // split-K partials
__device__ float g_bias3[3*ND];
__device__ __nv_bfloat16 g_qrb[(size_t)NROWS*NH*NR];  // qr in bf16

// split-bf16 activation buffers (hi/lo)
__device__ __nv_bfloat16 g_xh[NROWS*ND],  g_xl[NROWS*ND];
__device__ __nv_bfloat16 g_qh[NROWS*ND],  g_ql[NROWS*ND];
__device__ __nv_bfloat16 g_oh[NROWS*ND],  g_ol[NROWS*ND];
__device__ __nv_bfloat16 g_hh[NROWS*NDFF], g_hl[NROWS*NDFF];
// weight split buffers
__device__ __nv_bfloat16 g_Bh[(size_t)NV*ND];
__device__ __nv_bfloat16 g_Bl[(size_t)NV*ND];

// ---------------- helpers ----------------
__device__ __forceinline__ uint32_t smem_u32(const void* p) {
    uint32_t a;
    asm("{ .reg .u64 t; cvta.to.shared.u64 t, %1; cvt.u32.u64 %0, t; }" : "=r"(a) : "l"(p));
    return a;
}

#define LDSM4(r, a) \
    asm volatile("ldmatrix.sync.aligned.m8n8.x4.shared.b16 {%0,%1,%2,%3}, [%4];" \
        : "=r"((r)[0]), "=r"((r)[1]), "=r"((r)[2]), "=r"((r)[3]) : "r"(a))
#define LDSM2(r, a) \
    asm volatile("ldmatrix.sync.aligned.m8n8.x2.shared.b16 {%0,%1}, [%2];" \
        : "=r"((r)[0]), "=r"((r)[1]) : "r"(a))

#define MMA16816(d, a, b) \
    asm volatile("mma.sync.aligned.m16n8k16.row.col.f32.bf16.bf16.f32 " \
        "{%0,%1,%2,%3}, {%4,%5,%6,%7}, {%8,%9}, {%0,%1,%2,%3};" \
        : "+f"((d)[0]), "+f"((d)[1]), "+f"((d)[2]), "+f"((d)[3]) \
        : "r"((a)[0]), "r"((a)[1]), "r"((a)[2]), "r"((a)[3]), "r"((b)[0]), "r"((b)[1]))

#define CP_ASYNC16(dst, src, sz) \
    asm volatile("cp.async.cg.shared.global [%0], [%1], 16, %2;" \
        :: "r"(dst), "l"(src), "r"(sz))
#define CP_COMMIT() asm volatile("cp.async.commit_group;")
#define CP_WAIT0()  asm volatile("cp.async.wait_group 0;")
#define CP_WAIT1()  asm volatile("cp.async.wait_group 1;")

__device__ __forceinline__ void split2(float v0, float v1,
                                       __nv_bfloat16* hi, __nv_bfloat16* lo) {
    __nv_bfloat16 h0 = __float2bfloat16(v0);
    __nv_bfloat16 h1 = __float2bfloat16(v1);
    __nv_bfloat16 l0 = __float2bfloat16(v0 - __bfloat162float(h0));
    __nv_bfloat16 l1 = __float2bfloat16(v1 - __bfloat162float(h1));
    *reinterpret_cast<__nv_bfloat162*>(hi) = __nv_bfloat162(h0, h1);
    *reinterpret_cast<__nv_bfloat162*>(lo) = __nv_bfloat162(l0, l1);
}

// ---------------- fp32 -> bf16 hi/lo split (weights) ----------------
__global__ void split_kernel(const float4* __restrict__ src,
                             __nv_bfloat16* __restrict__ hi,
                             __nv_bfloat16* __restrict__ lo, int n4) {
    int i = blockIdx.x * 256 + threadIdx.x;
    if (i >= n4) return;
    float4 v = src[i];
    split2(v.x, v.y, hi + i*4,     lo + i*4);
    split2(v.z, v.w, hi + i*4 + 2, lo + i*4 + 2);
}

// ---------------- bias concat ----------------
__global__ void concat3_kernel(float* __restrict__ dst, const float* __restrict__ a,
                               const float* __restrict__ b, const float* __restrict__ c) {
    int i = blockIdx.x * 256 + threadIdx.x;
    if (i >= 3*ND) return;
    float v;
    if (i < ND) v = a[i];
    else if (i < 2*ND) v = b[i - ND];
    else v = c[i - 2*ND];
    dst[i] = v;
}

// ---------------- embedding: x = emb[tgt]*32, also emit hi/lo ----------------
__global__ void embed_kernel(const int* __restrict__ tgt,
                             const float* __restrict__ emb,
                             float* __restrict__ x,
                             __nv_bfloat16* __restrict__ xh,
                             __nv_bfloat16* __restrict__ xl) {
    int idx = blockIdx.x * blockDim.x + threadIdx.x;
    int row = idx >> 8;
    int c4  = idx & 255;
    float4 v = reinterpret_cast<const float4*>(emb + (size_t)tgt[row] * ND)[c4];
    v.x *= 32.f; v.y *= 32.f; v.z *= 32.f; v.w *= 32.f;
    reinterpret_cast<float4*>(x)[idx] = v;
    split2(v.x, v.y, xh + idx*4,     xl + idx*4);
    split2(v.z, v.w, xh + idx*4 + 2, xl + idx*4 + 2);
}

// ---------------- fused split-K reduce + residual + LayerNorm ----------------
// x <- LN(x + P0 + P1 + bias) * g + b, also emits xh/xl
__global__ __launch_bounds__(256) void red_ln_kernel(
    float* __restrict__ x, __nv_bfloat16* __restrict__ xh, __nv_bfloat16* __restrict__ xl,
    const float* __restrict__ P, const float* __restrict__ bias,
    const float* __restrict__ gw, const float* __restrict__ bw)
{
    __shared__ float buf[ND];
    __shared__ float red[33];
    int row = blockIdx.x;
    int tid = threadIdx.x;
    size_t base = (size_t)row * ND;
    const float* P0 = P + base;
    const float* P1 = P + (size_t)NROWS*ND + base;

    float s = 0.f;
    for (int d = tid; d < ND; d += 256) {
        float t = x[base + d] + P0[d] + P1[d] + bias[d];
        buf[d] = t;
        s += t;
    }
    #pragma unroll
    for (int off = 16; off; off >>= 1) s += __shfl_xor_sync(0xffffffffu, s, off);
    if ((tid & 31) == 0) red[tid >> 5] = s;
    __syncthreads();
    if (tid < 32) {
        float v2 = (tid < 8) ? red[tid] : 0.f;
        #pragma unroll
        for (int off = 4; off; off >>= 1) v2 += __shfl_xor_sync(0xffffffffu, v2, off);
        if (tid == 0) red[32] = v2;
    }
    __syncthreads();
    float mean = red[32] * (1.f/ND);

    float sv = 0.f;
    for (int d = tid; d < ND; d += 256) {
        float t = buf[d] - mean;
        sv += t*t;
    }
    #pragma unroll
    for (int off = 16; off; off >>= 1) sv += __shfl_xor_sync(0xffffffffu, sv, off);
    __syncthreads();
    if ((tid & 31) == 0) red[tid >> 5] = sv;
    __syncthreads();
    if (tid < 32) {
        float v2 = (tid < 8) ? red[tid] : 0.f;
        #pragma unroll
        for (int off = 4; off; off >>= 1) v2 += __shfl_xor_sync(0xffffffffu, v2, off);
        if (tid == 0) red[32] = v2;
    }
    __syncthreads();
    float inv = rsqrtf(red[32] * (1.f/ND) + 1e-5f);
    for (int d = tid*2; d < ND; d += 512) {
        float v0 = (buf[d]   - mean) * inv * gw[d]   + bw[d];
        float v1 = (buf[d+1] - mean) * inv * gw[d+1] + bw[d+1];
        x[base + d]   = v0;
        x[base + d+1] = v1;
        split2(v0, v1, xh + base + d, xl + base + d);
    }
}

// ---------------- split-bf16 tensor-core GEMM (mma.sync) ----------------
// 8 warps (2x4), CTA tile 128x128, k-tile 32, 3-stage cp.async pipeline.
// fp32 C (stride N, + split-K z-slice) and/or bf16 Ch/Cl, cols < Nh (row
// stride Nh; Cl null -> hi-only). Vector stores only when strides are even.
#define STG 32768
#define TOFF 8192
#define GEMM_SMEM (3*STG)

__device__ __forceinline__ void ld_tile_async(
    uint32_t sbase, const __nv_bfloat16* __restrict__ g,
    int ldk, int row0, int k0, int rmax, int tid)
{
    #pragma unroll
    for (int it = 0; it < 2; it++) {
        int qq = tid + it * 256;
        int r = qq >> 2, c = qq & 3;
        uint32_t dst = sbase + r * 64 + ((c ^ ((r >> 1) & 3)) << 4);
        int rr = (r < rmax) ? r : 0;
        const __nv_bfloat16* src = g + (size_t)(row0 + rr) * ldk + k0 + c * 8;
        int sz = (r < rmax) ? 16 : 0;
        CP_ASYNC16(dst, src, sz);
    }
}

__device__ __forceinline__ void ld_stage(
    uint32_t sbase, const __nv_bfloat16* Ah, const __nv_bfloat16* Al,
    const __nv_bfloat16* Bh, const __nv_bfloat16* Bl,
    int ldk, int m0, int n0, int k0, int bn, int tid, int terms)
{
    ld_tile_async(sbase + 0*TOFF, Ah, ldk, m0, k0, 128, tid);
    ld_tile_async(sbase + 2*TOFF, Bh, ldk, n0, k0, bn, tid);
    if (terms == 3) {
        ld_tile_async(sbase + 1*TOFF, Al, ldk, m0, k0, 128, tid);
        ld_tile_async(sbase + 3*TOFF, Bl, ldk, n0, k0, bn, tid);
    }
}

__global__ __launch_bounds__(256, 2) void gemm_tc(
    float* __restrict__ C, __nv_bfloat16* __restrict__ Ch, __nv_bfloat16* __restrict__ Cl,
    const __nv_bfloat16* __restrict__ Ah, const __nv_bfloat16* __restrict__ Al,
    const __nv_bfloat16* __restrict__ Bh, const __nv_bfloat16* __restrict__ Bl,
    const float* __restrict__ bias, int M, int N, int Nh, int K, int ldk,
    float alpha, int relu, int terms)
{
    extern __shared__ char sm[];
    uint32_t smb = smem_u32(sm);
    int tid = threadIdx.x;
    int wid = tid >> 5;
    int lane = tid & 31;
    int wm = wid & 1;
    int wn = wid >> 1;
    int m0 = blockIdx.y * 128;
    int n0 = blockIdx.x * 128;
    int kbase = blockIdx.z * K;
    if (C) C += (size_t)blockIdx.z * M * N;
    int NT = K >> 5;
    int bn = N - n0; if (bn > 128) bn = 128;

    ld_stage(smb, Ah, Al, Bh, Bl, ldk, m0, n0, kbase, bn, tid, terms);
    CP_COMMIT();
    if (NT > 1) {
        ld_stage(smb + STG, Ah, Al, Bh, Bl, ldk, m0, n0, kbase + 32, bn, tid, terms);
        CP_COMMIT();
    }

    float acc[4][4][4];
    #pragma unroll
    for (int i = 0; i < 4; i++)
        #pragma unroll
        for (int j = 0; j < 4; j++)
            #pragma unroll
            for (int e = 0; e < 4; e++) acc[i][j][e] = 0.f;

    int slot = 0, pslot = 2;
    for (int kt = 0; kt < NT; kt++) {
        if (kt + 1 < NT) { CP_WAIT1(); } else { CP_WAIT0(); }
        __syncthreads();

        if (kt + 2 < NT) {
            ld_stage(smb + pslot * STG, Ah, Al, Bh, Bl, ldk, m0, n0,
                     kbase + ((kt + 2) << 5), bn, tid, terms);
            CP_COMMIT();
        }

        uint32_t sA = smb + slot * STG;
        uint32_t sB = sA + 2*TOFF;

        #pragma unroll
        for (int ks = 0; ks < 2; ks++) {
            uint32_t ah[4][4], al[4][4], bh[4][2], bl[4][2];
            #pragma unroll
            for (int mf = 0; mf < 4; mf++) {
                int row = wm * 64 + mf * 16 + (lane & 15);
                int cc = ks * 2 + (lane >> 4);
                uint32_t ad = sA + row * 64 + (((cc ^ ((row >> 1) & 3))) << 4);
                LDSM4(ah[mf], ad);
                if (terms == 3) LDSM4(al[mf], ad + TOFF);
            }
            #pragma unroll
            for (int nf = 0; nf < 4; nf++) {
                int rn = wn * 32 + nf * 8 + (lane & 7);
                int cc = ks * 2 + ((lane >> 3) & 1);
                uint32_t bd = sB + rn * 64 + (((cc ^ ((rn >> 1) & 3))) << 4);
                LDSM2(bh[nf], bd);
                if (terms == 3) LDSM2(bl[nf], bd + TOFF);
            }
            #pragma unroll
            for (int mf = 0; mf < 4; mf++)
                #pragma unroll
                for (int nf = 0; nf < 4; nf++)
                    MMA16816(acc[mf][nf], ah[mf], bh[nf]);
            if (terms == 3) {
                #pragma unroll
                for (int mf = 0; mf < 4; mf++)
                    #pragma unroll
                    for (int nf = 0; nf < 4; nf++)
                        MMA16816(acc[mf][nf], ah[mf], bl[nf]);
                #pragma unroll
                for (int mf = 0; mf < 4; mf++)
                    #pragma unroll
                    for (int nf = 0; nf < 4; nf++)
                        MMA16816(acc[mf][nf], al[mf], bh[nf]);
            }
        }
        slot = (slot == 2) ? 0 : slot + 1;
        pslot = (pslot == 2) ? 0 : pslot + 1;
    }

    // epilogue: vector paths require even row strides (alignment!)
    bool fastC  = (C != nullptr)  && ((N & 1) == 0)  && (n0 + 128 <= N);
    bool fastCh = (Ch != nullptr) && ((Nh & 1) == 0) && (n0 + 128 <= Nh);
    #pragma unroll
    for (int mf = 0; mf < 4; mf++) {
        int r0 = m0 + wm * 64 + mf * 16 + (lane >> 2);
        #pragma unroll
        for (int half = 0; half < 2; half++) {
            int row = r0 + half * 8;
            size_t rbase = (size_t)row * N;
            size_t rbh   = (size_t)row * Nh;
            #pragma unroll
            for (int nf = 0; nf < 4; nf++) {
                int col = n0 + wn * 32 + nf * 8 + (lane & 3) * 2;
                float v0 = acc[mf][nf][half * 2 + 0];
                float v1 = acc[mf][nf][half * 2 + 1];
                if (bias) { v0 += bias[col]; v1 += __ldg(&bias[col + 1]); }
                v0 *= alpha; v1 *= alpha;
                if (relu) { v0 = fmaxf(v0, 0.f); v1 = fmaxf(v1, 0.f); }
                if (fastC) {
                    *reinterpret_cast<float2*>(C + rbase + col) = make_float2(v0, v1);
                } else if (C) {
                    if (col < N)     C[rbase + col] = v0;
                    if (col + 1 < N) C[rbase + col + 1] = v1;
                }
                if (fastCh) {
                    if (Cl) split2(v0, v1, Ch + rbh + col, Cl + rbh + col);
                    else *reinterpret_cast<__nv_bfloat162*>(Ch + rbh + col) =
                             __nv_bfloat162(__float2bfloat16(v0), __float2bfloat16(v1));
                } else if (Ch) {
                    // scalar fallback (odd Nh, e.g. QR's 2047): hi-only supported
                    if (col < Nh)     Ch[rbh + col] = __float2bfloat16(v0);
                    if (col + 1 < Nh) Ch[rbh + col + 1] = __float2bfloat16(v1);
                }
            }
        }
    }
}

// ---------------- fused attention (flash-style, exact softmax semantics) ----------------
// reads fused qkv (stride 3*ND, q scaled 0.125 at load), qr as bf16;
// writes o as bf16 hi/lo. ps-stash form (measured good).
#define QT 128
#define KT 64
#define LDQ 68
#define QKVS (3*ND)

__global__ __launch_bounds__(128, 2) void attn_kernel(
    __nv_bfloat16* __restrict__ oh, __nv_bfloat16* __restrict__ ol,
    const float* __restrict__ qkv, const __nv_bfloat16* __restrict__ qrb,
    const int* __restrict__ tgt)
{
    extern __shared__ float smf[];
    float* qs = smf;
    float* ks = qs + QT*LDQ;
    float* vs = ks + KT*LDQ;
    float* ps = vs + KT*LDQ;
    int*   pf = (int*)(ps + QT*LDQ);

    int b = blockIdx.z, h = blockIdx.y;
    int tid = threadIdx.x;
    int i0 = blockIdx.x * QT;
    int i  = i0 + tid;

    for (int t = tid; t < QT*NDH/4; t += 128) {
        int r  = t >> 4;
        int c4 = (t & 15) << 2;
        float4 va = *reinterpret_cast<const float4*>(
            &qkv[((size_t)(b*NS + i0 + r))*QKVS + h*NDH + c4]);
        va.x *= 0.125f; va.y *= 0.125f; va.z *= 0.125f; va.w *= 0.125f;
        *reinterpret_cast<float4*>(&qs[r*LDQ + c4]) = va;
    }

    float o[NDH];
    #pragma unroll
    for (int d = 0; d < NDH; d++) o[d] = 0.f;
    float m = -1e30f, l = 0.f;
    const __nv_bfloat16* qrrow = qrb + ((size_t)((b*NS + i)*NH + h)) * NR + (1023 - i);

    // causal tile skipping (bit-exact when key 0 is unmasked)
    int jend = (tgt[b*NS] == 0) ? NS : (i0 + QT);

    for (int j0 = 0; j0 < jend; j0 += KT) {
        __syncthreads();
        for (int t = tid; t < KT*NDH/4; t += 128) {
            int r  = t >> 4;
            int c4 = (t & 15) << 2;
            size_t g = ((size_t)(b*NS + j0 + r))*QKVS + h*NDH + c4;
            *reinterpret_cast<float4*>(&ks[r*LDQ + c4]) =
                *reinterpret_cast<const float4*>(&qkv[g + ND]);
            *reinterpret_cast<float4*>(&vs[r*LDQ + c4]) =
                *reinterpret_cast<const float4*>(&qkv[g + 2*ND]);
        }
        if (tid < KT) pf[tid] = (tgt[b*NS + j0 + tid] == 0) ? 1 : 0;
        __syncthreads();

        float s[KT];
        #pragma unroll
        for (int j = 0; j < KT; j++) s[j] = 0.f;
        #pragma unroll 1
        for (int d = 0; d < NDH; d += 4) {
            float4 qd = *reinterpret_cast<const float4*>(&qs[tid*LDQ + d]);
            #pragma unroll
            for (int j = 0; j < KT; j++) {
                float4 kj = *reinterpret_cast<const float4*>(&ks[j*LDQ + d]);
                s[j] += qd.x*kj.x + qd.y*kj.y + qd.z*kj.z + qd.w*kj.w;
            }
        }
        float mt = m;
        #pragma unroll
        for (int j = 0; j < KT; j++) {
            int jj = j0 + j;
            float val = s[j] + __bfloat162float(qrrow[jj]);
            if (jj > i || pf[j]) val = -1e9f;
            s[j] = val;
            mt = fmaxf(mt, val);
        }
        float corr = __expf(m - mt);
        m = mt;
        l *= corr;
        #pragma unroll
        for (int d = 0; d < NDH; d++) o[d] *= corr;
        #pragma unroll
        for (int j = 0; j < KT; j += 4) {
            float4 pv;
            pv.x = __expf(s[j]   - m);
            pv.y = __expf(s[j+1] - m);
            pv.z = __expf(s[j+2] - m);
            pv.w = __expf(s[j+3] - m);
            l += pv.x + pv.y + pv.z + pv.w;
            *reinterpret_cast<float4*>(&ps[tid*LDQ + j]) = pv;
        }
        #pragma unroll 1
        for (int j = 0; j < KT; j++) {
            float p = ps[tid*LDQ + j];
            #pragma unroll
            for (int d = 0; d < NDH; d += 4) {
                float4 vj = *reinterpret_cast<const float4*>(&vs[j*LDQ + d]);
                o[d]   += p*vj.x;
                o[d+1] += p*vj.y;
                o[d+2] += p*vj.z;
                o[d+3] += p*vj.w;
            }
        }
    }
    float inv = 1.f / l;
    size_t base = ((size_t)(b*NS + i))*ND + h*NDH;
    #pragma unroll
    for (int d = 0; d < NDH; d += 2)
        split2(o[d]*inv, o[d+1]*inv, oh + base + d, ol + base + d);
}

// ---------------- host orchestration ----------------
static inline void split(const float* src, __nv_bfloat16* hi, __nv_bfloat16* lo, size_t n) {
    int n4 = (int)(n / 4);
    split_kernel<<<(n4 + 255) / 256, 256>>>(
        reinterpret_cast<const float4*>(src), hi, lo, n4);
}

extern "C" void kernel_launch(void* const* d_in, const int* in_sizes, int n_in,
                              void* d_out, int out_size)
{
    (void)in_sizes; (void)n_in; (void)out_size;
    const int*   tgt = (const int*)d_in[0];
    const float* emb = (const float*)d_in[1];
    const float* Wq  = (const float*)d_in[2];
    const float* bq  = (const float*)d_in[3];
    const float* Wk  = (const float*)d_in[4];
    const float* bk  = (const float*)d_in[5];
    const float* Wv  = (const float*)d_in[6];
    const float* bv  = (const float*)d_in[7];
    const float* Wo  = (const float*)d_in[8];
    const float* bo  = (const float*)d_in[9];
    const float* rel = (const float*)d_in[10];
    const float* W1  = (const float*)d_in[11];
    const float* b1  = (const float*)d_in[12];
    const float* W2  = (const float*)d_in[13];
    const float* b2  = (const float*)d_in[14];
    const float* g1  = (const float*)d_in[15];
    const float* be1 = (const float*)d_in[16];
    const float* g2  = (const float*)d_in[17];
    const float* be2 = (const float*)d_in[18];
    const float* Wf  = (const float*)d_in[19];
    const float* bf  = (const float*)d_in[20];
    float* logits = (float*)d_out;

    float *x_, *qkv_, *p_, *bias3_;
    __nv_bfloat16 *qrb, *xh, *xl, *qh, *ql, *oh, *ol, *hh, *hl, *Bh, *Bl;
    cudaGetSymbolAddress((void**)&x_,    g_x);
    cudaGetSymbolAddress((void**)&qkv_,  g_qkv);
    cudaGetSymbolAddress((void**)&p_,    g_p);
    cudaGetSymbolAddress((void**)&bias3_, g_bias3);
    cudaGetSymbolAddress((void**)&qrb, g_qrb);
    cudaGetSymbolAddress((void**)&xh,  g_xh);
    cudaGetSymbolAddress((void**)&xl,  g_xl);
    cudaGetSymbolAddress((void**)&qh,  g_qh);
    cudaGetSymbolAddress((void**)&ql,  g_ql);
    cudaGetSymbolAddress((void**)&oh,  g_oh);
    cudaGetSymbolAddress((void**)&ol,  g_ol);
    cudaGetSymbolAddress((void**)&hh,  g_hh);
    cudaGetSymbolAddress((void**)&hl,  g_hl);
    cudaGetSymbolAddress((void**)&Bh,  g_Bh);
    cudaGetSymbolAddress((void**)&Bl,  g_Bl);

    int attn_smem = (QT*LDQ + KT*LDQ + KT*LDQ + QT*LDQ)*(int)sizeof(float) + KT*(int)sizeof(int);
    cudaFuncSetAttribute(attn_kernel, cudaFuncAttributeMaxDynamicSharedMemorySize, attn_smem);
    cudaFuncSetAttribute(gemm_tc, cudaFuncAttributeMaxDynamicSharedMemorySize, GEMM_SMEM);

    embed_kernel<<<NROWS*ND/4/256, 256>>>(tgt, emb, x_, xh, xl);

    __nv_bfloat16* nb = nullptr;
    float* nf = nullptr;

    for (int l = 0; l < NL; l++) {
        const size_t WDD = (size_t)ND*ND;
        // fused QKV projection: N=3072, grid (24,16), no split-K.
        // bf16 hi/lo emitted for q columns only (Nh=ND); q scale deferred.
        split(Wq + l*WDD, Bh,           Bl,           WDD);
        split(Wk + l*WDD, Bh + WDD,     Bl + WDD,     WDD);
        split(Wv + l*WDD, Bh + 2*WDD,   Bl + 2*WDD,   WDD);
        concat3_kernel<<<12, 256>>>(bias3_, bq + l*ND, bk + l*ND, bv + l*ND);
        gemm_tc<<<dim3(3*ND/128, NROWS/128), 256, GEMM_SMEM>>>(
            qkv_, qh, ql, xh, xl, Bh, Bl, bias3_, NROWS, 3*ND, ND, ND, ND, 1.f, 0, 3);

        // QR: single-term bf16, hi-only bf16 output (odd Nh -> scalar path),
        // alpha carries the q scale (exact power of two)
        split(rel + (size_t)l*NR*NDH, Bh, Bl, (size_t)NR*NDH);
        gemm_tc<<<dim3((NR + 127)/128, NROWS*NH/128), 256, GEMM_SMEM>>>(
            nf, qrb, nb, qh, ql, Bh, Bl, nf, NROWS*NH, NR, NR, NDH, NDH, 0.125f, 0, 1);

        attn_kernel<<<dim3(NS/QT, NH, NB), 128, attn_smem>>>(oh, ol, qkv_, qrb, tgt);

        // output projection (split-K=2) + fused reduce+LN
        split(Wo + l*WDD, Bh, Bl, WDD);
        gemm_tc<<<dim3(ND/128, NROWS/128, 2), 256, GEMM_SMEM>>>(
            p_, nb, nb, oh, ol, Bh, Bl, nf, NROWS, ND, ND, 512, ND, 1.f, 0, 3);
        red_ln_kernel<<<NROWS, 256>>>(x_, xh, xl, p_, bo + l*ND, g1 + l*ND, be1 + l*ND);

        // FFN1: write h directly as bf16 hi/lo
        split(W1 + (size_t)l*NDFF*ND, Bh, Bl, (size_t)NDFF*ND);
        gemm_tc<<<dim3(NDFF/128, NROWS/128), 256, GEMM_SMEM>>>(
            nf, hh, hl, xh, xl, Bh, Bl, b1 + l*NDFF, NROWS, NDFF, NDFF, ND, ND, 1.f, 1, 3);
        // FFN2 (split-K=2) + fused reduce+LN
        split(W2 + (size_t)l*ND*NDFF, Bh, Bl, (size_t)ND*NDFF);
        gemm_tc<<<dim3(ND/128, NROWS/128, 2), 256, GEMM_SMEM>>>(
            p_, nb, nb, hh, hl, Bh, Bl, nf, NROWS, ND, ND, 2048, NDFF, 1.f, 0, 3);
        red_ln_kernel<<<NROWS, 256>>>(x_, xh, xl, p_, b2 + l*ND, g2 + l*ND, be2 + l*ND);
    }

    // final logits: M=2048, N=32000, K=1024
    split(Wf, Bh, Bl, (size_t)NV*ND);
    gemm_tc<<<dim3(NV/128, NROWS/128), 256, GEMM_SMEM>>>(
        logits, nb, nb, xh, xl, Bh, Bl, bf, NROWS, NV, NV, ND, ND, 1.f, 0, 3);
}

// round 13
// speedup vs baseline: 1.0828x; 1.0828x over previous
#include <cuda_runtime.h>
#include <cuda_bf16.h>
#include <cstdint>
#include <math.h>

// ---------------- problem constants ----------------
#define NB 2
#define NS 1024
#define ND 1024
#define NH 16
#define NDH 64
#define NL 4
#define NDFF 4096
#define NV 32000
#define NRQ 1024             // qr columns actually used (rel idx 0..1023)
#define NROWS (NB*NS)        // 2048

// ---------------- scratch (static device allocations) ----------------
__device__ float g_x[NROWS*ND];
__device__ float g_qkv[NROWS*3*ND];                   // fused q|k|v, stride 3072
__device__ float g_p[2*NROWS*ND];                     // split-K partials
__device__ float g_bias3[3*ND];
__device__ __nv_bfloat16 g_qrb[(size_t)NROWS*NH*NRQ]; // qr in bf16 (1024 cols)
// attention split-KV partials
__device__ float g_po[2*NROWS*ND];
__device__ float g_pm[2*NROWS*NH];
__device__ float g_pl[2*NROWS*NH];

// split-bf16 activation buffers (hi/lo)
__device__ __nv_bfloat16 g_xh[NROWS*ND],  g_xl[NROWS*ND];
__device__ __nv_bfloat16 g_qh[NROWS*ND],  g_ql[NROWS*ND];
__device__ __nv_bfloat16 g_oh[NROWS*ND],  g_ol[NROWS*ND];
__device__ __nv_bfloat16 g_hh[NROWS*NDFF], g_hl[NROWS*NDFF];
// weight split buffers
__device__ __nv_bfloat16 g_Bh[(size_t)NV*ND];
__device__ __nv_bfloat16 g_Bl[(size_t)NV*ND];

// ---------------- helpers ----------------
__device__ __forceinline__ uint32_t smem_u32(const void* p) {
    uint32_t a;
    asm("{ .reg .u64 t; cvta.to.shared.u64 t, %1; cvt.u32.u64 %0, t; }" : "=r"(a) : "l"(p));
    return a;
}

#define LDSM4(r, a) \
    asm volatile("ldmatrix.sync.aligned.m8n8.x4.shared.b16 {%0,%1,%2,%3}, [%4];" \
        : "=r"((r)[0]), "=r"((r)[1]), "=r"((r)[2]), "=r"((r)[3]) : "r"(a))
#define LDSM2(r, a) \
    asm volatile("ldmatrix.sync.aligned.m8n8.x2.shared.b16 {%0,%1}, [%2];" \
        : "=r"((r)[0]), "=r"((r)[1]) : "r"(a))

#define MMA16816(d, a, b) \
    asm volatile("mma.sync.aligned.m16n8k16.row.col.f32.bf16.bf16.f32 " \
        "{%0,%1,%2,%3}, {%4,%5,%6,%7}, {%8,%9}, {%0,%1,%2,%3};" \
        : "+f"((d)[0]), "+f"((d)[1]), "+f"((d)[2]), "+f"((d)[3]) \
        : "r"((a)[0]), "r"((a)[1]), "r"((a)[2]), "r"((a)[3]), "r"((b)[0]), "r"((b)[1]))

#define CP_ASYNC16(dst, src, sz) \
    asm volatile("cp.async.cg.shared.global [%0], [%1], 16, %2;" \
        :: "r"(dst), "l"(src), "r"(sz))
#define CP_COMMIT() asm volatile("cp.async.commit_group;")
#define CP_WAIT0()  asm volatile("cp.async.wait_group 0;")
#define CP_WAIT1()  asm volatile("cp.async.wait_group 1;")

__device__ __forceinline__ void split2(float v0, float v1,
                                       __nv_bfloat16* hi, __nv_bfloat16* lo) {
    __nv_bfloat16 h0 = __float2bfloat16(v0);
    __nv_bfloat16 h1 = __float2bfloat16(v1);
    __nv_bfloat16 l0 = __float2bfloat16(v0 - __bfloat162float(h0));
    __nv_bfloat16 l1 = __float2bfloat16(v1 - __bfloat162float(h1));
    *reinterpret_cast<__nv_bfloat162*>(hi) = __nv_bfloat162(h0, h1);
    *reinterpret_cast<__nv_bfloat162*>(lo) = __nv_bfloat162(l0, l1);
}

// ---------------- fp32 -> bf16 hi/lo split (weights) ----------------
__global__ void split_kernel(const float4* __restrict__ src,
                             __nv_bfloat16* __restrict__ hi,
                             __nv_bfloat16* __restrict__ lo, int n4) {
    int i = blockIdx.x * 256 + threadIdx.x;
    if (i >= n4) return;
    float4 v = src[i];
    split2(v.x, v.y, hi + i*4,     lo + i*4);
    split2(v.z, v.w, hi + i*4 + 2, lo + i*4 + 2);
}

// ---------------- bias concat ----------------
__global__ void concat3_kernel(float* __restrict__ dst, const float* __restrict__ a,
                               const float* __restrict__ b, const float* __restrict__ c) {
    int i = blockIdx.x * 256 + threadIdx.x;
    if (i >= 3*ND) return;
    float v;
    if (i < ND) v = a[i];
    else if (i < 2*ND) v = b[i - ND];
    else v = c[i - 2*ND];
    dst[i] = v;
}

// ---------------- embedding: x = emb[tgt]*32, also emit hi/lo ----------------
__global__ void embed_kernel(const int* __restrict__ tgt,
                             const float* __restrict__ emb,
                             float* __restrict__ x,
                             __nv_bfloat16* __restrict__ xh,
                             __nv_bfloat16* __restrict__ xl) {
    int idx = blockIdx.x * blockDim.x + threadIdx.x;
    int row = idx >> 8;
    int c4  = idx & 255;
    float4 v = reinterpret_cast<const float4*>(emb + (size_t)tgt[row] * ND)[c4];
    v.x *= 32.f; v.y *= 32.f; v.z *= 32.f; v.w *= 32.f;
    reinterpret_cast<float4*>(x)[idx] = v;
    split2(v.x, v.y, xh + idx*4,     xl + idx*4);
    split2(v.z, v.w, xh + idx*4 + 2, xl + idx*4 + 2);
}

// ---------------- fused split-K reduce + residual + LayerNorm ----------------
__global__ __launch_bounds__(256) void red_ln_kernel(
    float* __restrict__ x, __nv_bfloat16* __restrict__ xh, __nv_bfloat16* __restrict__ xl,
    const float* __restrict__ P, const float* __restrict__ bias,
    const float* __restrict__ gw, const float* __restrict__ bw)
{
    __shared__ float buf[ND];
    __shared__ float red[33];
    int row = blockIdx.x;
    int tid = threadIdx.x;
    size_t base = (size_t)row * ND;
    const float* P0 = P + base;
    const float* P1 = P + (size_t)NROWS*ND + base;

    float s = 0.f;
    for (int d = tid; d < ND; d += 256) {
        float t = x[base + d] + P0[d] + P1[d] + bias[d];
        buf[d] = t;
        s += t;
    }
    #pragma unroll
    for (int off = 16; off; off >>= 1) s += __shfl_xor_sync(0xffffffffu, s, off);
    if ((tid & 31) == 0) red[tid >> 5] = s;
    __syncthreads();
    if (tid < 32) {
        float v2 = (tid < 8) ? red[tid] : 0.f;
        #pragma unroll
        for (int off = 4; off; off >>= 1) v2 += __shfl_xor_sync(0xffffffffu, v2, off);
        if (tid == 0) red[32] = v2;
    }
    __syncthreads();
    float mean = red[32] * (1.f/ND);

    float sv = 0.f;
    for (int d = tid; d < ND; d += 256) {
        float t = buf[d] - mean;
        sv += t*t;
    }
    #pragma unroll
    for (int off = 16; off; off >>= 1) sv += __shfl_xor_sync(0xffffffffu, sv, off);
    __syncthreads();
    if ((tid & 31) == 0) red[tid >> 5] = sv;
    __syncthreads();
    if (tid < 32) {
        float v2 = (tid < 8) ? red[tid] : 0.f;
        #pragma unroll
        for (int off = 4; off; off >>= 1) v2 += __shfl_xor_sync(0xffffffffu, v2, off);
        if (tid == 0) red[32] = v2;
    }
    __syncthreads();
    float inv = rsqrtf(red[32] * (1.f/ND) + 1e-5f);
    for (int d = tid*2; d < ND; d += 512) {
        float v0 = (buf[d]   - mean) * inv * gw[d]   + bw[d];
        float v1 = (buf[d+1] - mean) * inv * gw[d+1] + bw[d+1];
        x[base + d]   = v0;
        x[base + d+1] = v1;
        split2(v0, v1, xh + base + d, xl + base + d);
    }
}

// ---------------- split-bf16 tensor-core GEMM (mma.sync) ----------------
#define STG 32768
#define TOFF 8192
#define GEMM_SMEM (3*STG)

__device__ __forceinline__ void ld_tile_async(
    uint32_t sbase, const __nv_bfloat16* __restrict__ g,
    int ldk, int row0, int k0, int rmax, int tid)
{
    #pragma unroll
    for (int it = 0; it < 2; it++) {
        int qq = tid + it * 256;
        int r = qq >> 2, c = qq & 3;
        uint32_t dst = sbase + r * 64 + ((c ^ ((r >> 1) & 3)) << 4);
        int rr = (r < rmax) ? r : 0;
        const __nv_bfloat16* src = g + (size_t)(row0 + rr) * ldk + k0 + c * 8;
        int sz = (r < rmax) ? 16 : 0;
        CP_ASYNC16(dst, src, sz);
    }
}

__device__ __forceinline__ void ld_stage(
    uint32_t sbase, const __nv_bfloat16* Ah, const __nv_bfloat16* Al,
    const __nv_bfloat16* Bh, const __nv_bfloat16* Bl,
    int ldk, int m0, int n0, int k0, int bn, int tid, int terms)
{
    ld_tile_async(sbase + 0*TOFF, Ah, ldk, m0, k0, 128, tid);
    ld_tile_async(sbase + 2*TOFF, Bh, ldk, n0, k0, bn, tid);
    if (terms == 3) {
        ld_tile_async(sbase + 1*TOFF, Al, ldk, m0, k0, 128, tid);
        ld_tile_async(sbase + 3*TOFF, Bl, ldk, n0, k0, bn, tid);
    }
}

__global__ __launch_bounds__(256, 2) void gemm_tc(
    float* __restrict__ C, __nv_bfloat16* __restrict__ Ch, __nv_bfloat16* __restrict__ Cl,
    const __nv_bfloat16* __restrict__ Ah, const __nv_bfloat16* __restrict__ Al,
    const __nv_bfloat16* __restrict__ Bh, const __nv_bfloat16* __restrict__ Bl,
    const float* __restrict__ bias, int M, int N, int Nh, int K, int ldk,
    float alpha, int relu, int terms)
{
    extern __shared__ char sm[];
    uint32_t smb = smem_u32(sm);
    int tid = threadIdx.x;
    int wid = tid >> 5;
    int lane = tid & 31;
    int wm = wid & 1;
    int wn = wid >> 1;
    int m0 = blockIdx.y * 128;
    int n0 = blockIdx.x * 128;
    int kbase = blockIdx.z * K;
    if (C) C += (size_t)blockIdx.z * M * N;
    int NT = K >> 5;
    int bn = N - n0; if (bn > 128) bn = 128;

    ld_stage(smb, Ah, Al, Bh, Bl, ldk, m0, n0, kbase, bn, tid, terms);
    CP_COMMIT();
    if (NT > 1) {
        ld_stage(smb + STG, Ah, Al, Bh, Bl, ldk, m0, n0, kbase + 32, bn, tid, terms);
        CP_COMMIT();
    }

    float acc[4][4][4];
    #pragma unroll
    for (int i = 0; i < 4; i++)
        #pragma unroll
        for (int j = 0; j < 4; j++)
            #pragma unroll
            for (int e = 0; e < 4; e++) acc[i][j][e] = 0.f;

    int slot = 0, pslot = 2;
    for (int kt = 0; kt < NT; kt++) {
        if (kt + 1 < NT) { CP_WAIT1(); } else { CP_WAIT0(); }
        __syncthreads();

        if (kt + 2 < NT) {
            ld_stage(smb + pslot * STG, Ah, Al, Bh, Bl, ldk, m0, n0,
                     kbase + ((kt + 2) << 5), bn, tid, terms);
            CP_COMMIT();
        }

        uint32_t sA = smb + slot * STG;
        uint32_t sB = sA + 2*TOFF;

        #pragma unroll
        for (int ks = 0; ks < 2; ks++) {
            uint32_t ah[4][4], al[4][4], bh[4][2], bl[4][2];
            #pragma unroll
            for (int mf = 0; mf < 4; mf++) {
                int row = wm * 64 + mf * 16 + (lane & 15);
                int cc = ks * 2 + (lane >> 4);
                uint32_t ad = sA + row * 64 + (((cc ^ ((row >> 1) & 3))) << 4);
                LDSM4(ah[mf], ad);
                if (terms == 3) LDSM4(al[mf], ad + TOFF);
            }
            #pragma unroll
            for (int nf = 0; nf < 4; nf++) {
                int rn = wn * 32 + nf * 8 + (lane & 7);
                int cc = ks * 2 + ((lane >> 3) & 1);
                uint32_t bd = sB + rn * 64 + (((cc ^ ((rn >> 1) & 3))) << 4);
                LDSM2(bh[nf], bd);
                if (terms == 3) LDSM2(bl[nf], bd + TOFF);
            }
            #pragma unroll
            for (int mf = 0; mf < 4; mf++)
                #pragma unroll
                for (int nf = 0; nf < 4; nf++)
                    MMA16816(acc[mf][nf], ah[mf], bh[nf]);
            if (terms == 3) {
                #pragma unroll
                for (int mf = 0; mf < 4; mf++)
                    #pragma unroll
                    for (int nf = 0; nf < 4; nf++)
                        MMA16816(acc[mf][nf], ah[mf], bl[nf]);
                #pragma unroll
                for (int mf = 0; mf < 4; mf++)
                    #pragma unroll
                    for (int nf = 0; nf < 4; nf++)
                        MMA16816(acc[mf][nf], al[mf], bh[nf]);
            }
        }
        slot = (slot == 2) ? 0 : slot + 1;
        pslot = (pslot == 2) ? 0 : pslot + 1;
    }

    // epilogue: vector paths require even row strides (alignment!)
    bool fastC  = (C != nullptr)  && ((N & 1) == 0)  && (n0 + 128 <= N);
    bool fastCh = (Ch != nullptr) && ((Nh & 1) == 0) && (n0 + 128 <= Nh);
    #pragma unroll
    for (int mf = 0; mf < 4; mf++) {
        int r0 = m0 + wm * 64 + mf * 16 + (lane >> 2);
        #pragma unroll
        for (int half = 0; half < 2; half++) {
            int row = r0 + half * 8;
            size_t rbase = (size_t)row * N;
            size_t rbh   = (size_t)row * Nh;
            #pragma unroll
            for (int nf = 0; nf < 4; nf++) {
                int col = n0 + wn * 32 + nf * 8 + (lane & 3) * 2;
                float v0 = acc[mf][nf][half * 2 + 0];
                float v1 = acc[mf][nf][half * 2 + 1];
                if (bias) { v0 += bias[col]; v1 += __ldg(&bias[col + 1]); }
                v0 *= alpha; v1 *= alpha;
                if (relu) { v0 = fmaxf(v0, 0.f); v1 = fmaxf(v1, 0.f); }
                if (fastC) {
                    *reinterpret_cast<float2*>(C + rbase + col) = make_float2(v0, v1);
                } else if (C) {
                    if (col < N)     C[rbase + col] = v0;
                    if (col + 1 < N) C[rbase + col + 1] = v1;
                }
                if (fastCh) {
                    if (Cl) split2(v0, v1, Ch + rbh + col, Cl + rbh + col);
                    else *reinterpret_cast<__nv_bfloat162*>(Ch + rbh + col) =
                             __nv_bfloat162(__float2bfloat16(v0), __float2bfloat16(v1));
                } else if (Ch) {
                    if (col < Nh)     Ch[rbh + col] = __float2bfloat16(v0);
                    if (col + 1 < Nh) Ch[rbh + col + 1] = __float2bfloat16(v1);
                }
            }
        }
    }
}

// ---------------- fused attention, split-KV=2 (flash partials) ----------------
// grid (NS/QT, 2, NB*NH). Each CTA scans keys [split*512, min(jend,(split+1)*512)).
// Writes unnormalized o + (m,l) partials; combine kernel merges.
#define QT 128
#define KT 64
#define LDQ 68
#define QKVS (3*ND)
#define KVHALF 512

__global__ __launch_bounds__(128, 2) void attn_kernel(
    float* __restrict__ po, float* __restrict__ pm, float* __restrict__ pl,
    const float* __restrict__ qkv, const __nv_bfloat16* __restrict__ qrb,
    const int* __restrict__ tgt)
{
    extern __shared__ float smf[];
    float* qs = smf;
    float* ks = qs + QT*LDQ;
    float* vs = ks + KT*LDQ;
    float* ps = vs + KT*LDQ;
    int*   pf = (int*)(ps + QT*LDQ);

    int split = blockIdx.y;
    int bh = blockIdx.z;
    int b = bh >> 4, h = bh & 15;
    int tid = threadIdx.x;
    int i0 = blockIdx.x * QT;
    int i  = i0 + tid;

    float o[NDH];
    #pragma unroll
    for (int d = 0; d < NDH; d++) o[d] = 0.f;
    float m = -1e30f, l = 0.f;

    int jend = (tgt[b*NS] == 0) ? NS : (i0 + QT);
    int jstart = split * KVHALF;
    int jstop  = (jend < (split + 1) * KVHALF) ? jend : (split + 1) * KVHALF;

    if (jstart < jstop) {
        // load Q tile (scaled by 1/8, deferred from projection)
        for (int t = tid; t < QT*NDH/4; t += 128) {
            int r  = t >> 4;
            int c4 = (t & 15) << 2;
            float4 va = *reinterpret_cast<const float4*>(
                &qkv[((size_t)(b*NS + i0 + r))*QKVS + h*NDH + c4]);
            va.x *= 0.125f; va.y *= 0.125f; va.z *= 0.125f; va.w *= 0.125f;
            *reinterpret_cast<float4*>(&qs[r*LDQ + c4]) = va;
        }

        const __nv_bfloat16* qrrow =
            qrb + ((size_t)((b*NS + i)*NH + h)) * NRQ + (1023 - i);

        for (int j0 = jstart; j0 < jstop; j0 += KT) {
            __syncthreads();
            for (int t = tid; t < KT*NDH/4; t += 128) {
                int r  = t >> 4;
                int c4 = (t & 15) << 2;
                size_t g = ((size_t)(b*NS + j0 + r))*QKVS + h*NDH + c4;
                *reinterpret_cast<float4*>(&ks[r*LDQ + c4]) =
                    *reinterpret_cast<const float4*>(&qkv[g + ND]);
                *reinterpret_cast<float4*>(&vs[r*LDQ + c4]) =
                    *reinterpret_cast<const float4*>(&qkv[g + 2*ND]);
            }
            if (tid < KT) pf[tid] = (tgt[b*NS + j0 + tid] == 0) ? 1 : 0;
            __syncthreads();

            float s[KT];
            #pragma unroll
            for (int j = 0; j < KT; j++) s[j] = 0.f;
            #pragma unroll 1
            for (int d = 0; d < NDH; d += 4) {
                float4 qd = *reinterpret_cast<const float4*>(&qs[tid*LDQ + d]);
                #pragma unroll
                for (int j = 0; j < KT; j++) {
                    float4 kj = *reinterpret_cast<const float4*>(&ks[j*LDQ + d]);
                    s[j] += qd.x*kj.x + qd.y*kj.y + qd.z*kj.z + qd.w*kj.w;
                }
            }
            float mt = m;
            #pragma unroll
            for (int j = 0; j < KT; j++) {
                int jj = j0 + j;
                float val;
                if (jj > i || pf[j]) val = -1e9f;           // qr never read when masked
                else val = s[j] + __bfloat162float(qrrow[jj]);
                s[j] = val;
                mt = fmaxf(mt, val);
            }
            float corr = __expf(m - mt);
            m = mt;
            l *= corr;
            #pragma unroll
            for (int d = 0; d < NDH; d++) o[d] *= corr;
            #pragma unroll
            for (int j = 0; j < KT; j += 4) {
                float4 pv;
                pv.x = __expf(s[j]   - m);
                pv.y = __expf(s[j+1] - m);
                pv.z = __expf(s[j+2] - m);
                pv.w = __expf(s[j+3] - m);
                l += pv.x + pv.y + pv.z + pv.w;
                *reinterpret_cast<float4*>(&ps[tid*LDQ + j]) = pv;
            }
            #pragma unroll 1
            for (int j = 0; j < KT; j++) {
                float p = ps[tid*LDQ + j];
                #pragma unroll
                for (int d = 0; d < NDH; d += 4) {
                    float4 vj = *reinterpret_cast<const float4*>(&vs[j*LDQ + d]);
                    o[d]   += p*vj.x;
                    o[d+1] += p*vj.y;
                    o[d+2] += p*vj.z;
                    o[d+3] += p*vj.w;
                }
            }
        }
    }

    // write partials (unnormalized o, running m and l)
    size_t rh = (size_t)(b*NS + i)*NH + h + (size_t)split*NROWS*NH;
    pm[rh] = m;
    pl[rh] = l;
    size_t ob = (size_t)split*NROWS*ND + ((size_t)(b*NS + i))*ND + h*NDH;
    #pragma unroll
    for (int d = 0; d < NDH; d += 4)
        *reinterpret_cast<float4*>(&po[ob + d]) = make_float4(o[d], o[d+1], o[d+2], o[d+3]);
}

// ---------------- attention combine: merge 2 split-KV partials -> bf16 hi/lo ----------------
__global__ __launch_bounds__(256) void attn_combine(
    __nv_bfloat16* __restrict__ oh, __nv_bfloat16* __restrict__ ol,
    const float* __restrict__ po, const float* __restrict__ pm, const float* __restrict__ pl)
{
    int row = blockIdx.x;
    int tid = threadIdx.x;
    for (int e = tid*2; e < ND; e += 512) {
        int h = e >> 6;
        size_t rh = (size_t)row*NH + h;
        float m0 = pm[rh], m1 = pm[(size_t)NROWS*NH + rh];
        float l0 = pl[rh], l1 = pl[(size_t)NROWS*NH + rh];
        float m = fmaxf(m0, m1);
        float w0 = __expf(m0 - m), w1 = __expf(m1 - m);
        float inv = 1.f / (w0*l0 + w1*l1);
        size_t b0 = (size_t)row*ND + e;
        float v0 = (w0*po[b0]   + w1*po[(size_t)NROWS*ND + b0])   * inv;
        float v1 = (w0*po[b0+1] + w1*po[(size_t)NROWS*ND + b0+1]) * inv;
        split2(v0, v1, oh + b0, ol + b0);
    }
}

// ---------------- host orchestration ----------------
static inline void split(const float* src, __nv_bfloat16* hi, __nv_bfloat16* lo, size_t n) {
    int n4 = (int)(n / 4);
    split_kernel<<<(n4 + 255) / 256, 256>>>(
        reinterpret_cast<const float4*>(src), hi, lo, n4);
}

extern "C" void kernel_launch(void* const* d_in, const int* in_sizes, int n_in,
                              void* d_out, int out_size)
{
    (void)in_sizes; (void)n_in; (void)out_size;
    const int*   tgt = (const int*)d_in[0];
    const float* emb = (const float*)d_in[1];
    const float* Wq  = (const float*)d_in[2];
    const float* bq  = (const float*)d_in[3];
    const float* Wk  = (const float*)d_in[4];
    const float* bk  = (const float*)d_in[5];
    const float* Wv  = (const float*)d_in[6];
    const float* bv  = (const float*)d_in[7];
    const float* Wo  = (const float*)d_in[8];
    const float* bo  = (const float*)d_in[9];
    const float* rel = (const float*)d_in[10];
    const float* W1  = (const float*)d_in[11];
    const float* b1  = (const float*)d_in[12];
    const float* W2  = (const float*)d_in[13];
    const float* b2  = (const float*)d_in[14];
    const float* g1  = (const float*)d_in[15];
    const float* be1 = (const float*)d_in[16];
    const float* g2  = (const float*)d_in[17];
    const float* be2 = (const float*)d_in[18];
    const float* Wf  = (const float*)d_in[19];
    const float* bf  = (const float*)d_in[20];
    float* logits = (float*)d_out;

    float *x_, *qkv_, *p_, *bias3_, *po_, *pm_, *pl_;
    __nv_bfloat16 *qrb, *xh, *xl, *qh, *ql, *oh, *ol, *hh, *hl, *Bh, *Bl;
    cudaGetSymbolAddress((void**)&x_,    g_x);
    cudaGetSymbolAddress((void**)&qkv_,  g_qkv);
    cudaGetSymbolAddress((void**)&p_,    g_p);
    cudaGetSymbolAddress((void**)&bias3_, g_bias3);
    cudaGetSymbolAddress((void**)&po_,  g_po);
    cudaGetSymbolAddress((void**)&pm_,  g_pm);
    cudaGetSymbolAddress((void**)&pl_,  g_pl);
    cudaGetSymbolAddress((void**)&qrb, g_qrb);
    cudaGetSymbolAddress((void**)&xh,  g_xh);
    cudaGetSymbolAddress((void**)&xl,  g_xl);
    cudaGetSymbolAddress((void**)&qh,  g_qh);
    cudaGetSymbolAddress((void**)&ql,  g_ql);
    cudaGetSymbolAddress((void**)&oh,  g_oh);
    cudaGetSymbolAddress((void**)&ol,  g_ol);
    cudaGetSymbolAddress((void**)&hh,  g_hh);
    cudaGetSymbolAddress((void**)&hl,  g_hl);
    cudaGetSymbolAddress((void**)&Bh,  g_Bh);
    cudaGetSymbolAddress((void**)&Bl,  g_Bl);

    int attn_smem = (QT*LDQ + KT*LDQ + KT*LDQ + QT*LDQ)*(int)sizeof(float) + KT*(int)sizeof(int);
    cudaFuncSetAttribute(attn_kernel, cudaFuncAttributeMaxDynamicSharedMemorySize, attn_smem);
    cudaFuncSetAttribute(gemm_tc, cudaFuncAttributeMaxDynamicSharedMemorySize, GEMM_SMEM);

    embed_kernel<<<NROWS*ND/4/256, 256>>>(tgt, emb, x_, xh, xl);

    __nv_bfloat16* nb = nullptr;
    float* nf = nullptr;

    for (int l = 0; l < NL; l++) {
        const size_t WDD = (size_t)ND*ND;
        // fused QKV projection: N=3072, grid (24,16), no split-K
        split(Wq + l*WDD, Bh,         Bl,         WDD);
        split(Wk + l*WDD, Bh + WDD,   Bl + WDD,   WDD);
        split(Wv + l*WDD, Bh + 2*WDD, Bl + 2*WDD, WDD);
        concat3_kernel<<<12, 256>>>(bias3_, bq + l*ND, bk + l*ND, bv + l*ND);
        gemm_tc<<<dim3(3*ND/128, NROWS/128), 256, GEMM_SMEM>>>(
            qkv_, qh, ql, xh, xl, Bh, Bl, bias3_, NROWS, 3*ND, ND, ND, ND, 1.f, 0, 3);

        // QR: only the 1024 usable rel columns; single-term bf16, hi-only out,
        // alpha carries the exact 1/8 q scale. rel rows 0..1023 of the 2047.
        split(rel + (size_t)l*(2*NS-1)*NDH, Bh, Bl, (size_t)NRQ*NDH);
        gemm_tc<<<dim3(NRQ/128, NROWS*NH/128), 256, GEMM_SMEM>>>(
            nf, qrb, nb, qh, ql, Bh, Bl, nf, NROWS*NH, NRQ, NRQ, NDH, NDH, 0.125f, 0, 1);

        // attention: split-KV=2, then combine
        attn_kernel<<<dim3(NS/QT, 2, NB*NH), 128, attn_smem>>>(
            po_, pm_, pl_, qkv_, qrb, tgt);
        attn_combine<<<NROWS, 256>>>(oh, ol, po_, pm_, pl_);

        // output projection (split-K=2) + fused reduce+LN
        split(Wo + l*WDD, Bh, Bl, WDD);
        gemm_tc<<<dim3(ND/128, NROWS/128, 2), 256, GEMM_SMEM>>>(
            p_, nb, nb, oh, ol, Bh, Bl, nf, NROWS, ND, ND, 512, ND, 1.f, 0, 3);
        red_ln_kernel<<<NROWS, 256>>>(x_, xh, xl, p_, bo + l*ND, g1 + l*ND, be1 + l*ND);

        // FFN1: write h directly as bf16 hi/lo
        split(W1 + (size_t)l*NDFF*ND, Bh, Bl, (size_t)NDFF*ND);
        gemm_tc<<<dim3(NDFF/128, NROWS/128), 256, GEMM_SMEM>>>(
            nf, hh, hl, xh, xl, Bh, Bl, b1 + l*NDFF, NROWS, NDFF, NDFF, ND, ND, 1.f, 1, 3);
        // FFN2 (split-K=2) + fused reduce+LN
        split(W2 + (size_t)l*ND*NDFF, Bh, Bl, (size_t)ND*NDFF);
        gemm_tc<<<dim3(ND/128, NROWS/128, 2), 256, GEMM_SMEM>>>(
            p_, nb, nb, hh, hl, Bh, Bl, nf, NROWS, ND, ND, 2048, NDFF, 1.f, 0, 3);
        red_ln_kernel<<<NROWS, 256>>>(x_, xh, xl, p_, b2 + l*ND, g2 + l*ND, be2 + l*ND);
    }

    // final logits: M=2048, N=32000, K=1024
    split(Wf, Bh, Bl, (size_t)NV*ND);
    gemm_tc<<<dim3(NV/128, NROWS/128), 256, GEMM_SMEM>>>(
        logits, nb, nb, xh, xl, Bh, Bl, bf, NROWS, NV, NV, ND, ND, 1.f, 0, 3);
}

// round 14
// speedup vs baseline: 1.1500x; 1.0621x over previous
#include <cuda_runtime.h>
#include <cuda_bf16.h>
#include <cstdint>
#include <math.h>

// ---------------- problem constants ----------------
#define NB 2
#define NS 1024
#define ND 1024
#define NH 16
#define NDH 64
#define NL 4
#define NDFF 4096
#define NV 32000
#define NRQ 1024             // qr columns actually used (rel idx 0..1023)
#define NROWS (NB*NS)        // 2048
#define NSPLIT 4             // attention split-KV factor
#define KVSEG (NS/NSPLIT)    // 256

// ---------------- scratch (static device allocations) ----------------
__device__ float g_x[NROWS*ND];
__device__ float g_qkv[NROWS*3*ND];                   // fused q|k|v, stride 3072
__device__ float g_p[2*NROWS*ND];                     // split-K partials
__device__ float g_bias3[3*ND];
__device__ __nv_bfloat16 g_qrb[(size_t)NROWS*NH*NRQ]; // qr in bf16 (1024 cols)
// attention split-KV partials
__device__ float g_po[(size_t)NSPLIT*NROWS*ND];
__device__ float g_pm[NSPLIT*NROWS*NH];
__device__ float g_pl[NSPLIT*NROWS*NH];

// split-bf16 activation buffers (hi/lo)
__device__ __nv_bfloat16 g_xh[NROWS*ND],  g_xl[NROWS*ND];
__device__ __nv_bfloat16 g_qh[NROWS*ND],  g_ql[NROWS*ND];
__device__ __nv_bfloat16 g_oh[NROWS*ND],  g_ol[NROWS*ND];
__device__ __nv_bfloat16 g_hh[NROWS*NDFF], g_hl[NROWS*NDFF];
// weight split buffers
__device__ __nv_bfloat16 g_Bh[(size_t)NV*ND];
__device__ __nv_bfloat16 g_Bl[(size_t)NV*ND];

// ---------------- helpers ----------------
__device__ __forceinline__ uint32_t smem_u32(const void* p) {
    uint32_t a;
    asm("{ .reg .u64 t; cvta.to.shared.u64 t, %1; cvt.u32.u64 %0, t; }" : "=r"(a) : "l"(p));
    return a;
}

#define LDSM4(r, a) \
    asm volatile("ldmatrix.sync.aligned.m8n8.x4.shared.b16 {%0,%1,%2,%3}, [%4];" \
        : "=r"((r)[0]), "=r"((r)[1]), "=r"((r)[2]), "=r"((r)[3]) : "r"(a))
#define LDSM2(r, a) \
    asm volatile("ldmatrix.sync.aligned.m8n8.x2.shared.b16 {%0,%1}, [%2];" \
        : "=r"((r)[0]), "=r"((r)[1]) : "r"(a))

#define MMA16816(d, a, b) \
    asm volatile("mma.sync.aligned.m16n8k16.row.col.f32.bf16.bf16.f32 " \
        "{%0,%1,%2,%3}, {%4,%5,%6,%7}, {%8,%9}, {%0,%1,%2,%3};" \
        : "+f"((d)[0]), "+f"((d)[1]), "+f"((d)[2]), "+f"((d)[3]) \
        : "r"((a)[0]), "r"((a)[1]), "r"((a)[2]), "r"((a)[3]), "r"((b)[0]), "r"((b)[1]))

#define CP_ASYNC16(dst, src, sz) \
    asm volatile("cp.async.cg.shared.global [%0], [%1], 16, %2;" \
        :: "r"(dst), "l"(src), "r"(sz))
#define CP_COMMIT() asm volatile("cp.async.commit_group;")
#define CP_WAIT0()  asm volatile("cp.async.wait_group 0;")
#define CP_WAIT1()  asm volatile("cp.async.wait_group 1;")

__device__ __forceinline__ void split2(float v0, float v1,
                                       __nv_bfloat16* hi, __nv_bfloat16* lo) {
    __nv_bfloat16 h0 = __float2bfloat16(v0);
    __nv_bfloat16 h1 = __float2bfloat16(v1);
    __nv_bfloat16 l0 = __float2bfloat16(v0 - __bfloat162float(h0));
    __nv_bfloat16 l1 = __float2bfloat16(v1 - __bfloat162float(h1));
    *reinterpret_cast<__nv_bfloat162*>(hi) = __nv_bfloat162(h0, h1);
    *reinterpret_cast<__nv_bfloat162*>(lo) = __nv_bfloat162(l0, l1);
}

// ---------------- fp32 -> bf16 hi/lo split (weights) ----------------
__global__ void split_kernel(const float4* __restrict__ src,
                             __nv_bfloat16* __restrict__ hi,
                             __nv_bfloat16* __restrict__ lo, int n4) {
    int i = blockIdx.x * 256 + threadIdx.x;
    if (i >= n4) return;
    float4 v = src[i];
    split2(v.x, v.y, hi + i*4,     lo + i*4);
    split2(v.z, v.w, hi + i*4 + 2, lo + i*4 + 2);
}

// ---------------- 3-way weight split (QKV) in one launch ----------------
// seg = n4 per source; dst offsets seg*4 apart.
__global__ void split3_kernel(const float4* __restrict__ s0, const float4* __restrict__ s1,
                              const float4* __restrict__ s2,
                              __nv_bfloat16* __restrict__ hi,
                              __nv_bfloat16* __restrict__ lo, int seg) {
    int i = blockIdx.x * 256 + threadIdx.x;
    if (i >= 3*seg) return;
    const float4* src = (i < seg) ? s0 : (i < 2*seg ? s1 : s2);
    int j = (i < seg) ? i : (i < 2*seg ? i - seg : i - 2*seg);
    float4 v = src[j];
    split2(v.x, v.y, hi + (size_t)i*4,     lo + (size_t)i*4);
    split2(v.z, v.w, hi + (size_t)i*4 + 2, lo + (size_t)i*4 + 2);
}

// ---------------- bias concat ----------------
__global__ void concat3_kernel(float* __restrict__ dst, const float* __restrict__ a,
                               const float* __restrict__ b, const float* __restrict__ c) {
    int i = blockIdx.x * 256 + threadIdx.x;
    if (i >= 3*ND) return;
    float v;
    if (i < ND) v = a[i];
    else if (i < 2*ND) v = b[i - ND];
    else v = c[i - 2*ND];
    dst[i] = v;
}

// ---------------- embedding: x = emb[tgt]*32, also emit hi/lo ----------------
__global__ void embed_kernel(const int* __restrict__ tgt,
                             const float* __restrict__ emb,
                             float* __restrict__ x,
                             __nv_bfloat16* __restrict__ xh,
                             __nv_bfloat16* __restrict__ xl) {
    int idx = blockIdx.x * blockDim.x + threadIdx.x;
    int row = idx >> 8;
    int c4  = idx & 255;
    float4 v = reinterpret_cast<const float4*>(emb + (size_t)tgt[row] * ND)[c4];
    v.x *= 32.f; v.y *= 32.f; v.z *= 32.f; v.w *= 32.f;
    reinterpret_cast<float4*>(x)[idx] = v;
    split2(v.x, v.y, xh + idx*4,     xl + idx*4);
    split2(v.z, v.w, xh + idx*4 + 2, xl + idx*4 + 2);
}

// ---------------- fused split-K reduce + residual + LayerNorm ----------------
__global__ __launch_bounds__(256) void red_ln_kernel(
    float* __restrict__ x, __nv_bfloat16* __restrict__ xh, __nv_bfloat16* __restrict__ xl,
    const float* __restrict__ P, const float* __restrict__ bias,
    const float* __restrict__ gw, const float* __restrict__ bw)
{
    __shared__ float buf[ND];
    __shared__ float red[33];
    int row = blockIdx.x;
    int tid = threadIdx.x;
    size_t base = (size_t)row * ND;
    const float* P0 = P + base;
    const float* P1 = P + (size_t)NROWS*ND + base;

    float s = 0.f;
    for (int d = tid; d < ND; d += 256) {
        float t = x[base + d] + P0[d] + P1[d] + bias[d];
        buf[d] = t;
        s += t;
    }
    #pragma unroll
    for (int off = 16; off; off >>= 1) s += __shfl_xor_sync(0xffffffffu, s, off);
    if ((tid & 31) == 0) red[tid >> 5] = s;
    __syncthreads();
    if (tid < 32) {
        float v2 = (tid < 8) ? red[tid] : 0.f;
        #pragma unroll
        for (int off = 4; off; off >>= 1) v2 += __shfl_xor_sync(0xffffffffu, v2, off);
        if (tid == 0) red[32] = v2;
    }
    __syncthreads();
    float mean = red[32] * (1.f/ND);

    float sv = 0.f;
    for (int d = tid; d < ND; d += 256) {
        float t = buf[d] - mean;
        sv += t*t;
    }
    #pragma unroll
    for (int off = 16; off; off >>= 1) sv += __shfl_xor_sync(0xffffffffu, sv, off);
    __syncthreads();
    if ((tid & 31) == 0) red[tid >> 5] = sv;
    __syncthreads();
    if (tid < 32) {
        float v2 = (tid < 8) ? red[tid] : 0.f;
        #pragma unroll
        for (int off = 4; off; off >>= 1) v2 += __shfl_xor_sync(0xffffffffu, v2, off);
        if (tid == 0) red[32] = v2;
    }
    __syncthreads();
    float inv = rsqrtf(red[32] * (1.f/ND) + 1e-5f);
    for (int d = tid*2; d < ND; d += 512) {
        float v0 = (buf[d]   - mean) * inv * gw[d]   + bw[d];
        float v1 = (buf[d+1] - mean) * inv * gw[d+1] + bw[d+1];
        x[base + d]   = v0;
        x[base + d+1] = v1;
        split2(v0, v1, xh + base + d, xl + base + d);
    }
}

// ---------------- split-bf16 tensor-core GEMM (mma.sync) ----------------
#define STG 32768
#define TOFF 8192
#define GEMM_SMEM (3*STG)

__device__ __forceinline__ void ld_tile_async(
    uint32_t sbase, const __nv_bfloat16* __restrict__ g,
    int ldk, int row0, int k0, int rmax, int tid)
{
    #pragma unroll
    for (int it = 0; it < 2; it++) {
        int qq = tid + it * 256;
        int r = qq >> 2, c = qq & 3;
        uint32_t dst = sbase + r * 64 + ((c ^ ((r >> 1) & 3)) << 4);
        int rr = (r < rmax) ? r : 0;
        const __nv_bfloat16* src = g + (size_t)(row0 + rr) * ldk + k0 + c * 8;
        int sz = (r < rmax) ? 16 : 0;
        CP_ASYNC16(dst, src, sz);
    }
}

__device__ __forceinline__ void ld_stage(
    uint32_t sbase, const __nv_bfloat16* Ah, const __nv_bfloat16* Al,
    const __nv_bfloat16* Bh, const __nv_bfloat16* Bl,
    int ldk, int m0, int n0, int k0, int bn, int tid, int terms)
{
    ld_tile_async(sbase + 0*TOFF, Ah, ldk, m0, k0, 128, tid);
    ld_tile_async(sbase + 2*TOFF, Bh, ldk, n0, k0, bn, tid);
    if (terms == 3) {
        ld_tile_async(sbase + 1*TOFF, Al, ldk, m0, k0, 128, tid);
        ld_tile_async(sbase + 3*TOFF, Bl, ldk, n0, k0, bn, tid);
    }
}

__global__ __launch_bounds__(256, 2) void gemm_tc(
    float* __restrict__ C, __nv_bfloat16* __restrict__ Ch, __nv_bfloat16* __restrict__ Cl,
    const __nv_bfloat16* __restrict__ Ah, const __nv_bfloat16* __restrict__ Al,
    const __nv_bfloat16* __restrict__ Bh, const __nv_bfloat16* __restrict__ Bl,
    const float* __restrict__ bias, int M, int N, int Nh, int K, int ldk,
    float alpha, int relu, int terms)
{
    extern __shared__ char sm[];
    uint32_t smb = smem_u32(sm);
    int tid = threadIdx.x;
    int wid = tid >> 5;
    int lane = tid & 31;
    int wm = wid & 1;
    int wn = wid >> 1;
    int m0 = blockIdx.y * 128;
    int n0 = blockIdx.x * 128;
    int kbase = blockIdx.z * K;
    if (C) C += (size_t)blockIdx.z * M * N;
    int NT = K >> 5;
    int bn = N - n0; if (bn > 128) bn = 128;

    ld_stage(smb, Ah, Al, Bh, Bl, ldk, m0, n0, kbase, bn, tid, terms);
    CP_COMMIT();
    if (NT > 1) {
        ld_stage(smb + STG, Ah, Al, Bh, Bl, ldk, m0, n0, kbase + 32, bn, tid, terms);
        CP_COMMIT();
    }

    float acc[4][4][4];
    #pragma unroll
    for (int i = 0; i < 4; i++)
        #pragma unroll
        for (int j = 0; j < 4; j++)
            #pragma unroll
            for (int e = 0; e < 4; e++) acc[i][j][e] = 0.f;

    int slot = 0, pslot = 2;
    for (int kt = 0; kt < NT; kt++) {
        if (kt + 1 < NT) { CP_WAIT1(); } else { CP_WAIT0(); }
        __syncthreads();

        if (kt + 2 < NT) {
            ld_stage(smb + pslot * STG, Ah, Al, Bh, Bl, ldk, m0, n0,
                     kbase + ((kt + 2) << 5), bn, tid, terms);
            CP_COMMIT();
        }

        uint32_t sA = smb + slot * STG;
        uint32_t sB = sA + 2*TOFF;

        #pragma unroll
        for (int ks = 0; ks < 2; ks++) {
            uint32_t ah[4][4], al[4][4], bh[4][2], bl[4][2];
            #pragma unroll
            for (int mf = 0; mf < 4; mf++) {
                int row = wm * 64 + mf * 16 + (lane & 15);
                int cc = ks * 2 + (lane >> 4);
                uint32_t ad = sA + row * 64 + (((cc ^ ((row >> 1) & 3))) << 4);
                LDSM4(ah[mf], ad);
                if (terms == 3) LDSM4(al[mf], ad + TOFF);
            }
            #pragma unroll
            for (int nf = 0; nf < 4; nf++) {
                int rn = wn * 32 + nf * 8 + (lane & 7);
                int cc = ks * 2 + ((lane >> 3) & 1);
                uint32_t bd = sB + rn * 64 + (((cc ^ ((rn >> 1) & 3))) << 4);
                LDSM2(bh[nf], bd);
                if (terms == 3) LDSM2(bl[nf], bd + TOFF);
            }
            #pragma unroll
            for (int mf = 0; mf < 4; mf++)
                #pragma unroll
                for (int nf = 0; nf < 4; nf++)
                    MMA16816(acc[mf][nf], ah[mf], bh[nf]);
            if (terms == 3) {
                #pragma unroll
                for (int mf = 0; mf < 4; mf++)
                    #pragma unroll
                    for (int nf = 0; nf < 4; nf++)
                        MMA16816(acc[mf][nf], ah[mf], bl[nf]);
                #pragma unroll
                for (int mf = 0; mf < 4; mf++)
                    #pragma unroll
                    for (int nf = 0; nf < 4; nf++)
                        MMA16816(acc[mf][nf], al[mf], bh[nf]);
            }
        }
        slot = (slot == 2) ? 0 : slot + 1;
        pslot = (pslot == 2) ? 0 : pslot + 1;
    }

    // epilogue: vector paths require even row strides (alignment!)
    bool fastC  = (C != nullptr)  && ((N & 1) == 0)  && (n0 + 128 <= N);
    bool fastCh = (Ch != nullptr) && ((Nh & 1) == 0) && (n0 + 128 <= Nh);
    #pragma unroll
    for (int mf = 0; mf < 4; mf++) {
        int r0 = m0 + wm * 64 + mf * 16 + (lane >> 2);
        #pragma unroll
        for (int half = 0; half < 2; half++) {
            int row = r0 + half * 8;
            size_t rbase = (size_t)row * N;
            size_t rbh   = (size_t)row * Nh;
            #pragma unroll
            for (int nf = 0; nf < 4; nf++) {
                int col = n0 + wn * 32 + nf * 8 + (lane & 3) * 2;
                float v0 = acc[mf][nf][half * 2 + 0];
                float v1 = acc[mf][nf][half * 2 + 1];
                if (bias) { v0 += bias[col]; v1 += __ldg(&bias[col + 1]); }
                v0 *= alpha; v1 *= alpha;
                if (relu) { v0 = fmaxf(v0, 0.f); v1 = fmaxf(v1, 0.f); }
                if (fastC) {
                    *reinterpret_cast<float2*>(C + rbase + col) = make_float2(v0, v1);
                } else if (C) {
                    if (col < N)     C[rbase + col] = v0;
                    if (col + 1 < N) C[rbase + col + 1] = v1;
                }
                if (fastCh) {
                    if (Cl) split2(v0, v1, Ch + rbh + col, Cl + rbh + col);
                    else *reinterpret_cast<__nv_bfloat162*>(Ch + rbh + col) =
                             __nv_bfloat162(__float2bfloat16(v0), __float2bfloat16(v1));
                } else if (Ch) {
                    if (col < Nh)     Ch[rbh + col] = __float2bfloat16(v0);
                    if (col + 1 < Nh) Ch[rbh + col + 1] = __float2bfloat16(v1);
                }
            }
        }
    }
}

// ---------------- fused attention, split-KV=4 (flash partials) ----------------
// grid (NS/QT, NSPLIT, NB*NH). CTA scans keys [split*KVSEG, min(jend,(split+1)*KVSEG)).
#define QT 128
#define KT 64
#define LDQ 68
#define QKVS (3*ND)

__global__ __launch_bounds__(128, 2) void attn_kernel(
    float* __restrict__ po, float* __restrict__ pm, float* __restrict__ pl,
    const float* __restrict__ qkv, const __nv_bfloat16* __restrict__ qrb,
    const int* __restrict__ tgt)
{
    extern __shared__ float smf[];
    float* qs = smf;
    float* ks = qs + QT*LDQ;
    float* vs = ks + KT*LDQ;
    float* ps = vs + KT*LDQ;
    int*   pf = (int*)(ps + QT*LDQ);

    int split = blockIdx.y;
    int bh = blockIdx.z;
    int b = bh >> 4, h = bh & 15;
    int tid = threadIdx.x;
    int i0 = blockIdx.x * QT;
    int i  = i0 + tid;

    float o[NDH];
    #pragma unroll
    for (int d = 0; d < NDH; d++) o[d] = 0.f;
    float m = -1e30f, l = 0.f;

    int jend = (tgt[b*NS] == 0) ? NS : (i0 + QT);
    int jstart = split * KVSEG;
    int jstop  = (jend < (split + 1) * KVSEG) ? jend : (split + 1) * KVSEG;

    if (jstart < jstop) {
        for (int t = tid; t < QT*NDH/4; t += 128) {
            int r  = t >> 4;
            int c4 = (t & 15) << 2;
            float4 va = *reinterpret_cast<const float4*>(
                &qkv[((size_t)(b*NS + i0 + r))*QKVS + h*NDH + c4]);
            va.x *= 0.125f; va.y *= 0.125f; va.z *= 0.125f; va.w *= 0.125f;
            *reinterpret_cast<float4*>(&qs[r*LDQ + c4]) = va;
        }

        const __nv_bfloat16* qrrow =
            qrb + ((size_t)((b*NS + i)*NH + h)) * NRQ + (1023 - i);

        for (int j0 = jstart; j0 < jstop; j0 += KT) {
            __syncthreads();
            for (int t = tid; t < KT*NDH/4; t += 128) {
                int r  = t >> 4;
                int c4 = (t & 15) << 2;
                size_t g = ((size_t)(b*NS + j0 + r))*QKVS + h*NDH + c4;
                *reinterpret_cast<float4*>(&ks[r*LDQ + c4]) =
                    *reinterpret_cast<const float4*>(&qkv[g + ND]);
                *reinterpret_cast<float4*>(&vs[r*LDQ + c4]) =
                    *reinterpret_cast<const float4*>(&qkv[g + 2*ND]);
            }
            if (tid < KT) pf[tid] = (tgt[b*NS + j0 + tid] == 0) ? 1 : 0;
            __syncthreads();

            float s[KT];
            #pragma unroll
            for (int j = 0; j < KT; j++) s[j] = 0.f;
            #pragma unroll 1
            for (int d = 0; d < NDH; d += 4) {
                float4 qd = *reinterpret_cast<const float4*>(&qs[tid*LDQ + d]);
                #pragma unroll
                for (int j = 0; j < KT; j++) {
                    float4 kj = *reinterpret_cast<const float4*>(&ks[j*LDQ + d]);
                    s[j] += qd.x*kj.x + qd.y*kj.y + qd.z*kj.z + qd.w*kj.w;
                }
            }
            float mt = m;
            #pragma unroll
            for (int j = 0; j < KT; j++) {
                int jj = j0 + j;
                float val;
                if (jj > i || pf[j]) val = -1e9f;
                else val = s[j] + __bfloat162float(qrrow[jj]);
                s[j] = val;
                mt = fmaxf(mt, val);
            }
            float corr = __expf(m - mt);
            m = mt;
            l *= corr;
            #pragma unroll
            for (int d = 0; d < NDH; d++) o[d] *= corr;
            #pragma unroll
            for (int j = 0; j < KT; j += 4) {
                float4 pv;
                pv.x = __expf(s[j]   - m);
                pv.y = __expf(s[j+1] - m);
                pv.z = __expf(s[j+2] - m);
                pv.w = __expf(s[j+3] - m);
                l += pv.x + pv.y + pv.z + pv.w;
                *reinterpret_cast<float4*>(&ps[tid*LDQ + j]) = pv;
            }
            #pragma unroll 1
            for (int j = 0; j < KT; j++) {
                float p = ps[tid*LDQ + j];
                #pragma unroll
                for (int d = 0; d < NDH; d += 4) {
                    float4 vj = *reinterpret_cast<const float4*>(&vs[j*LDQ + d]);
                    o[d]   += p*vj.x;
                    o[d+1] += p*vj.y;
                    o[d+2] += p*vj.z;
                    o[d+3] += p*vj.w;
                }
            }
        }
    }

    size_t rh = (size_t)(b*NS + i)*NH + h + (size_t)split*NROWS*NH;
    pm[rh] = m;
    pl[rh] = l;
    size_t ob = (size_t)split*NROWS*ND + ((size_t)(b*NS + i))*ND + h*NDH;
    #pragma unroll
    for (int d = 0; d < NDH; d += 4)
        *reinterpret_cast<float4*>(&po[ob + d]) = make_float4(o[d], o[d+1], o[d+2], o[d+3]);
}

// ---------------- attention combine: merge NSPLIT partials -> bf16 hi/lo ----------------
__global__ __launch_bounds__(256) void attn_combine(
    __nv_bfloat16* __restrict__ oh, __nv_bfloat16* __restrict__ ol,
    const float* __restrict__ po, const float* __restrict__ pm, const float* __restrict__ pl)
{
    int row = blockIdx.x;
    int tid = threadIdx.x;
    for (int e = tid*2; e < ND; e += 512) {
        int h = e >> 6;
        size_t rh = (size_t)row*NH + h;
        float ms[NSPLIT], ls[NSPLIT];
        float m = -1e30f;
        #pragma unroll
        for (int s = 0; s < NSPLIT; s++) {
            ms[s] = pm[(size_t)s*NROWS*NH + rh];
            ls[s] = pl[(size_t)s*NROWS*NH + rh];
            m = fmaxf(m, ms[s]);
        }
        float denom = 0.f;
        float w[NSPLIT];
        #pragma unroll
        for (int s = 0; s < NSPLIT; s++) {
            w[s] = __expf(ms[s] - m);
            denom += w[s] * ls[s];
        }
        float inv = 1.f / denom;
        size_t b0 = (size_t)row*ND + e;
        float v0 = 0.f, v1 = 0.f;
        #pragma unroll
        for (int s = 0; s < NSPLIT; s++) {
            size_t sb = (size_t)s*NROWS*ND + b0;
            v0 += w[s] * po[sb];
            v1 += w[s] * po[sb + 1];
        }
        v0 *= inv; v1 *= inv;
        split2(v0, v1, oh + b0, ol + b0);
    }
}

// ---------------- host orchestration ----------------
static inline void split(const float* src, __nv_bfloat16* hi, __nv_bfloat16* lo, size_t n) {
    int n4 = (int)(n / 4);
    split_kernel<<<(n4 + 255) / 256, 256>>>(
        reinterpret_cast<const float4*>(src), hi, lo, n4);
}

extern "C" void kernel_launch(void* const* d_in, const int* in_sizes, int n_in,
                              void* d_out, int out_size)
{
    (void)in_sizes; (void)n_in; (void)out_size;
    const int*   tgt = (const int*)d_in[0];
    const float* emb = (const float*)d_in[1];
    const float* Wq  = (const float*)d_in[2];
    const float* bq  = (const float*)d_in[3];
    const float* Wk  = (const float*)d_in[4];
    const float* bk  = (const float*)d_in[5];
    const float* Wv  = (const float*)d_in[6];
    const float* bv  = (const float*)d_in[7];
    const float* Wo  = (const float*)d_in[8];
    const float* bo  = (const float*)d_in[9];
    const float* rel = (const float*)d_in[10];
    const float* W1  = (const float*)d_in[11];
    const float* b1  = (const float*)d_in[12];
    const float* W2  = (const float*)d_in[13];
    const float* b2  = (const float*)d_in[14];
    const float* g1  = (const float*)d_in[15];
    const float* be1 = (const float*)d_in[16];
    const float* g2  = (const float*)d_in[17];
    const float* be2 = (const float*)d_in[18];
    const float* Wf  = (const float*)d_in[19];
    const float* bf  = (const float*)d_in[20];
    float* logits = (float*)d_out;

    float *x_, *qkv_, *p_, *bias3_, *po_, *pm_, *pl_;
    __nv_bfloat16 *qrb, *xh, *xl, *qh, *ql, *oh, *ol, *hh, *hl, *Bh, *Bl;
    cudaGetSymbolAddress((void**)&x_,    g_x);
    cudaGetSymbolAddress((void**)&qkv_,  g_qkv);
    cudaGetSymbolAddress((void**)&p_,    g_p);
    cudaGetSymbolAddress((void**)&bias3_, g_bias3);
    cudaGetSymbolAddress((void**)&po_,  g_po);
    cudaGetSymbolAddress((void**)&pm_,  g_pm);
    cudaGetSymbolAddress((void**)&pl_,  g_pl);
    cudaGetSymbolAddress((void**)&qrb, g_qrb);
    cudaGetSymbolAddress((void**)&xh,  g_xh);
    cudaGetSymbolAddress((void**)&xl,  g_xl);
    cudaGetSymbolAddress((void**)&qh,  g_qh);
    cudaGetSymbolAddress((void**)&ql,  g_ql);
    cudaGetSymbolAddress((void**)&oh,  g_oh);
    cudaGetSymbolAddress((void**)&ol,  g_ol);
    cudaGetSymbolAddress((void**)&hh,  g_hh);
    cudaGetSymbolAddress((void**)&hl,  g_hl);
    cudaGetSymbolAddress((void**)&Bh,  g_Bh);
    cudaGetSymbolAddress((void**)&Bl,  g_Bl);

    int attn_smem = (QT*LDQ + KT*LDQ + KT*LDQ + QT*LDQ)*(int)sizeof(float) + KT*(int)sizeof(int);
    cudaFuncSetAttribute(attn_kernel, cudaFuncAttributeMaxDynamicSharedMemorySize, attn_smem);
    cudaFuncSetAttribute(gemm_tc, cudaFuncAttributeMaxDynamicSharedMemorySize, GEMM_SMEM);

    embed_kernel<<<NROWS*ND/4/256, 256>>>(tgt, emb, x_, xh, xl);

    __nv_bfloat16* nb = nullptr;
    float* nf = nullptr;

    for (int l = 0; l < NL; l++) {
        const size_t WDD = (size_t)ND*ND;
        // fused QKV projection: one split launch for Wq|Wk|Wv
        split3_kernel<<<(int)(3*WDD/4 + 255)/256, 256>>>(
            reinterpret_cast<const float4*>(Wq + l*WDD),
            reinterpret_cast<const float4*>(Wk + l*WDD),
            reinterpret_cast<const float4*>(Wv + l*WDD),
            Bh, Bl, (int)(WDD/4));
        concat3_kernel<<<12, 256>>>(bias3_, bq + l*ND, bk + l*ND, bv + l*ND);
        gemm_tc<<<dim3(3*ND/128, NROWS/128), 256, GEMM_SMEM>>>(
            qkv_, qh, ql, xh, xl, Bh, Bl, bias3_, NROWS, 3*ND, ND, ND, ND, 1.f, 0, 3);

        // QR: 1024 usable rel columns; single-term bf16, hi-only out; alpha = 1/8
        split(rel + (size_t)l*(2*NS-1)*NDH, Bh, Bl, (size_t)NRQ*NDH);
        gemm_tc<<<dim3(NRQ/128, NROWS*NH/128), 256, GEMM_SMEM>>>(
            nf, qrb, nb, qh, ql, Bh, Bl, nf, NROWS*NH, NRQ, NRQ, NDH, NDH, 0.125f, 0, 1);

        // attention: split-KV=4, then combine
        attn_kernel<<<dim3(NS/QT, NSPLIT, NB*NH), 128, attn_smem>>>(
            po_, pm_, pl_, qkv_, qrb, tgt);
        attn_combine<<<NROWS, 256>>>(oh, ol, po_, pm_, pl_);

        // output projection (split-K=2) + fused reduce+LN
        split(Wo + l*WDD, Bh, Bl, WDD);
        gemm_tc<<<dim3(ND/128, NROWS/128, 2), 256, GEMM_SMEM>>>(
            p_, nb, nb, oh, ol, Bh, Bl, nf, NROWS, ND, ND, 512, ND, 1.f, 0, 3);
        red_ln_kernel<<<NROWS, 256>>>(x_, xh, xl, p_, bo + l*ND, g1 + l*ND, be1 + l*ND);

        // FFN1: write h directly as bf16 hi/lo
        split(W1 + (size_t)l*NDFF*ND, Bh, Bl, (size_t)NDFF*ND);
        gemm_tc<<<dim3(NDFF/128, NROWS/128), 256, GEMM_SMEM>>>(
            nf, hh, hl, xh, xl, Bh, Bl, b1 + l*NDFF, NROWS, NDFF, NDFF, ND, ND, 1.f, 1, 3);
        // FFN2 (split-K=2) + fused reduce+LN
        split(W2 + (size_t)l*ND*NDFF, Bh, Bl, (size_t)ND*NDFF);
        gemm_tc<<<dim3(ND/128, NROWS/128, 2), 256, GEMM_SMEM>>>(
            p_, nb, nb, hh, hl, Bh, Bl, nf, NROWS, ND, ND, 2048, NDFF, 1.f, 0, 3);
        red_ln_kernel<<<NROWS, 256>>>(x_, xh, xl, p_, b2 + l*ND, g2 + l*ND, be2 + l*ND);
    }

    // final logits: M=2048, N=32000, K=1024
    split(Wf, Bh, Bl, (size_t)NV*ND);
    gemm_tc<<<dim3(NV/128, NROWS/128), 256, GEMM_SMEM>>>(
        logits, nb, nb, xh, xl, Bh, Bl, bf, NROWS, NV, NV, ND, ND, 1.f, 0, 3);
}

// round 15
// speedup vs baseline: 1.1809x; 1.0268x over previous
#include <cuda_runtime.h>
#include <cuda_bf16.h>
#include <cstdint>
#include <math.h>

// ---------------- problem constants ----------------
#define NB 2
#define NS 1024
#define ND 1024
#define NH 16
#define NDH 64
#define NL 4
#define NDFF 4096
#define NV 32000
#define NRQ 1024             // qr columns actually used (rel idx 0..1023)
#define NROWS (NB*NS)        // 2048
#define NSPLIT 4             // attention split-KV factor
#define KVSEG (NS/NSPLIT)    // 256
#define WDDE (ND*ND)         // 1M elements per DxD weight

// ---------------- scratch (static device allocations) ----------------
__device__ float g_x[NROWS*ND];
__device__ float g_qkv[NROWS*3*ND];                   // fused q|k|v, stride 3072
__device__ float g_p[2*NROWS*ND];                     // split-K partials
__device__ float g_bias3[3*ND];
__device__ __nv_bfloat16 g_qrb[(size_t)NROWS*NH*NRQ]; // qr in bf16 (1024 cols)
// attention split-KV partials
__device__ float g_po[(size_t)NSPLIT*NROWS*ND];
__device__ float g_pm[NSPLIT*NROWS*NH];
__device__ float g_pl[NSPLIT*NROWS*NH];

// split-bf16 activation buffers (hi/lo)
__device__ __nv_bfloat16 g_xh[NROWS*ND],  g_xl[NROWS*ND];
__device__ __nv_bfloat16 g_qh[NROWS*ND],  g_ql[NROWS*ND];
__device__ __nv_bfloat16 g_oh[NROWS*ND],  g_ol[NROWS*ND];
__device__ __nv_bfloat16 g_hh[NROWS*NDFF], g_hl[NROWS*NDFF];
// weight split buffers (layer layout: QKV[0,3W) Wo[3W,4W) W1[4W,8W) W2[8W,12W) rel[12W,+64K))
__device__ __nv_bfloat16 g_Bh[(size_t)NV*ND];
__device__ __nv_bfloat16 g_Bl[(size_t)NV*ND];

// ---------------- helpers ----------------
__device__ __forceinline__ uint32_t smem_u32(const void* p) {
    uint32_t a;
    asm("{ .reg .u64 t; cvta.to.shared.u64 t, %1; cvt.u32.u64 %0, t; }" : "=r"(a) : "l"(p));
    return a;
}

#define LDSM4(r, a) \
    asm volatile("ldmatrix.sync.aligned.m8n8.x4.shared.b16 {%0,%1,%2,%3}, [%4];" \
        : "=r"((r)[0]), "=r"((r)[1]), "=r"((r)[2]), "=r"((r)[3]) : "r"(a))
#define LDSM2(r, a) \
    asm volatile("ldmatrix.sync.aligned.m8n8.x2.shared.b16 {%0,%1}, [%2];" \
        : "=r"((r)[0]), "=r"((r)[1]) : "r"(a))

#define MMA16816(d, a, b) \
    asm volatile("mma.sync.aligned.m16n8k16.row.col.f32.bf16.bf16.f32 " \
        "{%0,%1,%2,%3}, {%4,%5,%6,%7}, {%8,%9}, {%0,%1,%2,%3};" \
        : "+f"((d)[0]), "+f"((d)[1]), "+f"((d)[2]), "+f"((d)[3]) \
        : "r"((a)[0]), "r"((a)[1]), "r"((a)[2]), "r"((a)[3]), "r"((b)[0]), "r"((b)[1]))

#define CP_ASYNC16(dst, src, sz) \
    asm volatile("cp.async.cg.shared.global [%0], [%1], 16, %2;" \
        :: "r"(dst), "l"(src), "r"(sz))
#define CP_COMMIT() asm volatile("cp.async.commit_group;")
#define CP_WAIT0()  asm volatile("cp.async.wait_group 0;")
#define CP_WAIT1()  asm volatile("cp.async.wait_group 1;")

__device__ __forceinline__ void split2(float v0, float v1,
                                       __nv_bfloat16* hi, __nv_bfloat16* lo) {
    __nv_bfloat16 h0 = __float2bfloat16(v0);
    __nv_bfloat16 h1 = __float2bfloat16(v1);
    __nv_bfloat16 l0 = __float2bfloat16(v0 - __bfloat162float(h0));
    __nv_bfloat16 l1 = __float2bfloat16(v1 - __bfloat162float(h1));
    *reinterpret_cast<__nv_bfloat162*>(hi) = __nv_bfloat162(h0, h1);
    *reinterpret_cast<__nv_bfloat162*>(lo) = __nv_bfloat162(l0, l1);
}

// ---------------- fp32 -> bf16 hi/lo split (single source; used for Wf) ----------------
__global__ void split_kernel(const float4* __restrict__ src,
                             __nv_bfloat16* __restrict__ hi,
                             __nv_bfloat16* __restrict__ lo, int n4) {
    int i = blockIdx.x * 256 + threadIdx.x;
    if (i >= n4) return;
    float4 v = src[i];
    split2(v.x, v.y, hi + i*4,     lo + i*4);
    split2(v.z, v.w, hi + i*4 + 2, lo + i*4 + 2);
}

// ---------------- per-layer mega split: QKV | Wo | W1 | W2 | rel in one launch ----------------
// s = WDDE/4 float4 units per DxD weight; relq = NRQ*NDH/4.
__global__ void megasplit_kernel(
    const float4* __restrict__ wq, const float4* __restrict__ wk,
    const float4* __restrict__ wv, const float4* __restrict__ wo,
    const float4* __restrict__ w1, const float4* __restrict__ w2,
    const float4* __restrict__ rl,
    __nv_bfloat16* __restrict__ hi, __nv_bfloat16* __restrict__ lo,
    int s, int relq)
{
    int i = blockIdx.x * 256 + threadIdx.x;
    int total = 12*s + relq;
    if (i >= total) return;
    const float4* src;
    int j;
    if (i < 3*s) {
        if (i < s)        { src = wq; j = i; }
        else if (i < 2*s) { src = wk; j = i - s; }
        else              { src = wv; j = i - 2*s; }
    } else if (i < 4*s)   { src = wo; j = i - 3*s; }
    else if (i < 8*s)     { src = w1; j = i - 4*s; }
    else if (i < 12*s)    { src = w2; j = i - 8*s; }
    else                  { src = rl; j = i - 12*s; }
    float4 v = src[j];
    split2(v.x, v.y, hi + (size_t)i*4,     lo + (size_t)i*4);
    split2(v.z, v.w, hi + (size_t)i*4 + 2, lo + (size_t)i*4 + 2);
}

// ---------------- bias concat ----------------
__global__ void concat3_kernel(float* __restrict__ dst, const float* __restrict__ a,
                               const float* __restrict__ b, const float* __restrict__ c) {
    int i = blockIdx.x * 256 + threadIdx.x;
    if (i >= 3*ND) return;
    float v;
    if (i < ND) v = a[i];
    else if (i < 2*ND) v = b[i - ND];
    else v = c[i - 2*ND];
    dst[i] = v;
}

// ---------------- embedding: x = emb[tgt]*32, also emit hi/lo ----------------
__global__ void embed_kernel(const int* __restrict__ tgt,
                             const float* __restrict__ emb,
                             float* __restrict__ x,
                             __nv_bfloat16* __restrict__ xh,
                             __nv_bfloat16* __restrict__ xl) {
    int idx = blockIdx.x * blockDim.x + threadIdx.x;
    int row = idx >> 8;
    int c4  = idx & 255;
    float4 v = reinterpret_cast<const float4*>(emb + (size_t)tgt[row] * ND)[c4];
    v.x *= 32.f; v.y *= 32.f; v.z *= 32.f; v.w *= 32.f;
    reinterpret_cast<float4*>(x)[idx] = v;
    split2(v.x, v.y, xh + idx*4,     xl + idx*4);
    split2(v.z, v.w, xh + idx*4 + 2, xl + idx*4 + 2);
}

// ---------------- fused split-K reduce + residual + LayerNorm ----------------
__global__ __launch_bounds__(256) void red_ln_kernel(
    float* __restrict__ x, __nv_bfloat16* __restrict__ xh, __nv_bfloat16* __restrict__ xl,
    const float* __restrict__ P, const float* __restrict__ bias,
    const float* __restrict__ gw, const float* __restrict__ bw)
{
    __shared__ float buf[ND];
    __shared__ float red[33];
    int row = blockIdx.x;
    int tid = threadIdx.x;
    size_t base = (size_t)row * ND;
    const float* P0 = P + base;
    const float* P1 = P + (size_t)NROWS*ND + base;

    float s = 0.f;
    for (int d = tid; d < ND; d += 256) {
        float t = x[base + d] + P0[d] + P1[d] + bias[d];
        buf[d] = t;
        s += t;
    }
    #pragma unroll
    for (int off = 16; off; off >>= 1) s += __shfl_xor_sync(0xffffffffu, s, off);
    if ((tid & 31) == 0) red[tid >> 5] = s;
    __syncthreads();
    if (tid < 32) {
        float v2 = (tid < 8) ? red[tid] : 0.f;
        #pragma unroll
        for (int off = 4; off; off >>= 1) v2 += __shfl_xor_sync(0xffffffffu, v2, off);
        if (tid == 0) red[32] = v2;
    }
    __syncthreads();
    float mean = red[32] * (1.f/ND);

    float sv = 0.f;
    for (int d = tid; d < ND; d += 256) {
        float t = buf[d] - mean;
        sv += t*t;
    }
    #pragma unroll
    for (int off = 16; off; off >>= 1) sv += __shfl_xor_sync(0xffffffffu, sv, off);
    __syncthreads();
    if ((tid & 31) == 0) red[tid >> 5] = sv;
    __syncthreads();
    if (tid < 32) {
        float v2 = (tid < 8) ? red[tid] : 0.f;
        #pragma unroll
        for (int off = 4; off; off >>= 1) v2 += __shfl_xor_sync(0xffffffffu, v2, off);
        if (tid == 0) red[32] = v2;
    }
    __syncthreads();
    float inv = rsqrtf(red[32] * (1.f/ND) + 1e-5f);
    for (int d = tid*2; d < ND; d += 512) {
        float v0 = (buf[d]   - mean) * inv * gw[d]   + bw[d];
        float v1 = (buf[d+1] - mean) * inv * gw[d+1] + bw[d+1];
        x[base + d]   = v0;
        x[base + d+1] = v1;
        split2(v0, v1, xh + base + d, xl + base + d);
    }
}

// ---------------- split-bf16 tensor-core GEMM (mma.sync) ----------------
#define STG 32768
#define TOFF 8192
#define GEMM_SMEM (3*STG)

__device__ __forceinline__ void ld_tile_async(
    uint32_t sbase, const __nv_bfloat16* __restrict__ g,
    int ldk, int row0, int k0, int rmax, int tid)
{
    #pragma unroll
    for (int it = 0; it < 2; it++) {
        int qq = tid + it * 256;
        int r = qq >> 2, c = qq & 3;
        uint32_t dst = sbase + r * 64 + ((c ^ ((r >> 1) & 3)) << 4);
        int rr = (r < rmax) ? r : 0;
        const __nv_bfloat16* src = g + (size_t)(row0 + rr) * ldk + k0 + c * 8;
        int sz = (r < rmax) ? 16 : 0;
        CP_ASYNC16(dst, src, sz);
    }
}

__device__ __forceinline__ void ld_stage(
    uint32_t sbase, const __nv_bfloat16* Ah, const __nv_bfloat16* Al,
    const __nv_bfloat16* Bh, const __nv_bfloat16* Bl,
    int ldk, int m0, int n0, int k0, int bn, int tid, int terms)
{
    ld_tile_async(sbase + 0*TOFF, Ah, ldk, m0, k0, 128, tid);
    ld_tile_async(sbase + 2*TOFF, Bh, ldk, n0, k0, bn, tid);
    if (terms == 3) {
        ld_tile_async(sbase + 1*TOFF, Al, ldk, m0, k0, 128, tid);
        ld_tile_async(sbase + 3*TOFF, Bl, ldk, n0, k0, bn, tid);
    }
}

__global__ __launch_bounds__(256, 2) void gemm_tc(
    float* __restrict__ C, __nv_bfloat16* __restrict__ Ch, __nv_bfloat16* __restrict__ Cl,
    const __nv_bfloat16* __restrict__ Ah, const __nv_bfloat16* __restrict__ Al,
    const __nv_bfloat16* __restrict__ Bh, const __nv_bfloat16* __restrict__ Bl,
    const float* __restrict__ bias, int M, int N, int Nh, int K, int ldk,
    float alpha, int relu, int terms, int tri)
{
    extern __shared__ char sm[];
    uint32_t smb = smem_u32(sm);
    int tid = threadIdx.x;
    int wid = tid >> 5;
    int lane = tid & 31;
    int wm = wid & 1;
    int wn = wid >> 1;
    int m0 = blockIdx.y * 128;
    int n0 = blockIdx.x * 128;

    // triangular skip (QR): rows m0..m0+127 encode i = (row>>4) mod 1024;
    // a column block is dead iff n0+127 < 1023 - i_max = 1016 - i_min.
    if (tri) {
        int imin = (m0 >> 4) & (NS - 1);
        if (n0 + 127 < 1016 - imin) return;
    }

    int kbase = blockIdx.z * K;
    if (C) C += (size_t)blockIdx.z * M * N;
    int NT = K >> 5;
    int bn = N - n0; if (bn > 128) bn = 128;

    ld_stage(smb, Ah, Al, Bh, Bl, ldk, m0, n0, kbase, bn, tid, terms);
    CP_COMMIT();
    if (NT > 1) {
        ld_stage(smb + STG, Ah, Al, Bh, Bl, ldk, m0, n0, kbase + 32, bn, tid, terms);
        CP_COMMIT();
    }

    float acc[4][4][4];
    #pragma unroll
    for (int i = 0; i < 4; i++)
        #pragma unroll
        for (int j = 0; j < 4; j++)
            #pragma unroll
            for (int e = 0; e < 4; e++) acc[i][j][e] = 0.f;

    int slot = 0, pslot = 2;
    for (int kt = 0; kt < NT; kt++) {
        if (kt + 1 < NT) { CP_WAIT1(); } else { CP_WAIT0(); }
        __syncthreads();

        if (kt + 2 < NT) {
            ld_stage(smb + pslot * STG, Ah, Al, Bh, Bl, ldk, m0, n0,
                     kbase + ((kt + 2) << 5), bn, tid, terms);
            CP_COMMIT();
        }

        uint32_t sA = smb + slot * STG;
        uint32_t sB = sA + 2*TOFF;

        #pragma unroll
        for (int ks = 0; ks < 2; ks++) {
            uint32_t ah[4][4], al[4][4], bh[4][2], bl[4][2];
            #pragma unroll
            for (int mf = 0; mf < 4; mf++) {
                int row = wm * 64 + mf * 16 + (lane & 15);
                int cc = ks * 2 + (lane >> 4);
                uint32_t ad = sA + row * 64 + (((cc ^ ((row >> 1) & 3))) << 4);
                LDSM4(ah[mf], ad);
                if (terms == 3) LDSM4(al[mf], ad + TOFF);
            }
            #pragma unroll
            for (int nf = 0; nf < 4; nf++) {
                int rn = wn * 32 + nf * 8 + (lane & 7);
                int cc = ks * 2 + ((lane >> 3) & 1);
                uint32_t bd = sB + rn * 64 + (((cc ^ ((rn >> 1) & 3))) << 4);
                LDSM2(bh[nf], bd);
                if (terms == 3) LDSM2(bl[nf], bd + TOFF);
            }
            #pragma unroll
            for (int mf = 0; mf < 4; mf++)
                #pragma unroll
                for (int nf = 0; nf < 4; nf++)
                    MMA16816(acc[mf][nf], ah[mf], bh[nf]);
            if (terms == 3) {
                #pragma unroll
                for (int mf = 0; mf < 4; mf++)
                    #pragma unroll
                    for (int nf = 0; nf < 4; nf++)
                        MMA16816(acc[mf][nf], ah[mf], bl[nf]);
                #pragma unroll
                for (int mf = 0; mf < 4; mf++)
                    #pragma unroll
                    for (int nf = 0; nf < 4; nf++)
                        MMA16816(acc[mf][nf], al[mf], bh[nf]);
            }
        }
        slot = (slot == 2) ? 0 : slot + 1;
        pslot = (pslot == 2) ? 0 : pslot + 1;
    }

    // epilogue: vector paths require even row strides (alignment!)
    bool fastC  = (C != nullptr)  && ((N & 1) == 0)  && (n0 + 128 <= N);
    bool fastCh = (Ch != nullptr) && ((Nh & 1) == 0) && (n0 + 128 <= Nh);
    #pragma unroll
    for (int mf = 0; mf < 4; mf++) {
        int r0 = m0 + wm * 64 + mf * 16 + (lane >> 2);
        #pragma unroll
        for (int half = 0; half < 2; half++) {
            int row = r0 + half * 8;
            size_t rbase = (size_t)row * N;
            size_t rbh   = (size_t)row * Nh;
            #pragma unroll
            for (int nf = 0; nf < 4; nf++) {
                int col = n0 + wn * 32 + nf * 8 + (lane & 3) * 2;
                float v0 = acc[mf][nf][half * 2 + 0];
                float v1 = acc[mf][nf][half * 2 + 1];
                if (bias) { v0 += bias[col]; v1 += __ldg(&bias[col + 1]); }
                v0 *= alpha; v1 *= alpha;
                if (relu) { v0 = fmaxf(v0, 0.f); v1 = fmaxf(v1, 0.f); }
                if (fastC) {
                    *reinterpret_cast<float2*>(C + rbase + col) = make_float2(v0, v1);
                } else if (C) {
                    if (col < N)     C[rbase + col] = v0;
                    if (col + 1 < N) C[rbase + col + 1] = v1;
                }
                if (fastCh) {
                    if (Cl) split2(v0, v1, Ch + rbh + col, Cl + rbh + col);
                    else *reinterpret_cast<__nv_bfloat162*>(Ch + rbh + col) =
                             __nv_bfloat162(__float2bfloat16(v0), __float2bfloat16(v1));
                } else if (Ch) {
                    if (col < Nh)     Ch[rbh + col] = __float2bfloat16(v0);
                    if (col + 1 < Nh) Ch[rbh + col + 1] = __float2bfloat16(v1);
                }
            }
        }
    }
}

// ---------------- fused attention, split-KV=4 (flash partials) ----------------
#define QT 128
#define KT 64
#define LDQ 68
#define QKVS (3*ND)

__global__ __launch_bounds__(128, 2) void attn_kernel(
    float* __restrict__ po, float* __restrict__ pm, float* __restrict__ pl,
    const float* __restrict__ qkv, const __nv_bfloat16* __restrict__ qrb,
    const int* __restrict__ tgt)
{
    extern __shared__ float smf[];
    float* qs = smf;
    float* ks = qs + QT*LDQ;
    float* vs = ks + KT*LDQ;
    float* ps = vs + KT*LDQ;
    int*   pf = (int*)(ps + QT*LDQ);

    int split = blockIdx.y;
    int bh = blockIdx.z;
    int b = bh >> 4, h = bh & 15;
    int tid = threadIdx.x;
    int i0 = blockIdx.x * QT;
    int i  = i0 + tid;

    float o[NDH];
    #pragma unroll
    for (int d = 0; d < NDH; d++) o[d] = 0.f;
    float m = -1e30f, l = 0.f;

    int jend = (tgt[b*NS] == 0) ? NS : (i0 + QT);
    int jstart = split * KVSEG;
    int jstop  = (jend < (split + 1) * KVSEG) ? jend : (split + 1) * KVSEG;

    if (jstart < jstop) {
        for (int t = tid; t < QT*NDH/4; t += 128) {
            int r  = t >> 4;
            int c4 = (t & 15) << 2;
            float4 va = *reinterpret_cast<const float4*>(
                &qkv[((size_t)(b*NS + i0 + r))*QKVS + h*NDH + c4]);
            va.x *= 0.125f; va.y *= 0.125f; va.z *= 0.125f; va.w *= 0.125f;
            *reinterpret_cast<float4*>(&qs[r*LDQ + c4]) = va;
        }

        const __nv_bfloat16* qrrow =
            qrb + ((size_t)((b*NS + i)*NH + h)) * NRQ + (1023 - i);

        for (int j0 = jstart; j0 < jstop; j0 += KT) {
            __syncthreads();
            for (int t = tid; t < KT*NDH/4; t += 128) {
                int r  = t >> 4;
                int c4 = (t & 15) << 2;
                size_t g = ((size_t)(b*NS + j0 + r))*QKVS + h*NDH + c4;
                *reinterpret_cast<float4*>(&ks[r*LDQ + c4]) =
                    *reinterpret_cast<const float4*>(&qkv[g + ND]);
                *reinterpret_cast<float4*>(&vs[r*LDQ + c4]) =
                    *reinterpret_cast<const float4*>(&qkv[g + 2*ND]);
            }
            if (tid < KT) pf[tid] = (tgt[b*NS + j0 + tid] == 0) ? 1 : 0;
            __syncthreads();

            float s[KT];
            #pragma unroll
            for (int j = 0; j < KT; j++) s[j] = 0.f;
            #pragma unroll 1
            for (int d = 0; d < NDH; d += 4) {
                float4 qd = *reinterpret_cast<const float4*>(&qs[tid*LDQ + d]);
                #pragma unroll
                for (int j = 0; j < KT; j++) {
                    float4 kj = *reinterpret_cast<const float4*>(&ks[j*LDQ + d]);
                    s[j] += qd.x*kj.x + qd.y*kj.y + qd.z*kj.z + qd.w*kj.w;
                }
            }
            float mt = m;
            #pragma unroll
            for (int j = 0; j < KT; j++) {
                int jj = j0 + j;
                float val;
                if (jj > i || pf[j]) val = -1e9f;
                else val = s[j] + __bfloat162float(qrrow[jj]);
                s[j] = val;
                mt = fmaxf(mt, val);
            }
            float corr = __expf(m - mt);
            m = mt;
            l *= corr;
            #pragma unroll
            for (int d = 0; d < NDH; d++) o[d] *= corr;
            #pragma unroll
            for (int j = 0; j < KT; j += 4) {
                float4 pv;
                pv.x = __expf(s[j]   - m);
                pv.y = __expf(s[j+1] - m);
                pv.z = __expf(s[j+2] - m);
                pv.w = __expf(s[j+3] - m);
                l += pv.x + pv.y + pv.z + pv.w;
                *reinterpret_cast<float4*>(&ps[tid*LDQ + j]) = pv;
            }
            #pragma unroll 1
            for (int j = 0; j < KT; j++) {
                float p = ps[tid*LDQ + j];
                #pragma unroll
                for (int d = 0; d < NDH; d += 4) {
                    float4 vj = *reinterpret_cast<const float4*>(&vs[j*LDQ + d]);
                    o[d]   += p*vj.x;
                    o[d+1] += p*vj.y;
                    o[d+2] += p*vj.z;
                    o[d+3] += p*vj.w;
                }
            }
        }
    }

    size_t rh = (size_t)(b*NS + i)*NH + h + (size_t)split*NROWS*NH;
    pm[rh] = m;
    pl[rh] = l;
    size_t ob = (size_t)split*NROWS*ND + ((size_t)(b*NS + i))*ND + h*NDH;
    #pragma unroll
    for (int d = 0; d < NDH; d += 4)
        *reinterpret_cast<float4*>(&po[ob + d]) = make_float4(o[d], o[d+1], o[d+2], o[d+3]);
}

// ---------------- attention combine: merge NSPLIT partials -> bf16 hi/lo ----------------
__global__ __launch_bounds__(256) void attn_combine(
    __nv_bfloat16* __restrict__ oh, __nv_bfloat16* __restrict__ ol,
    const float* __restrict__ po, const float* __restrict__ pm, const float* __restrict__ pl)
{
    int row = blockIdx.x;
    int tid = threadIdx.x;
    for (int e = tid*2; e < ND; e += 512) {
        int h = e >> 6;
        size_t rh = (size_t)row*NH + h;
        float ms[NSPLIT], ls[NSPLIT];
        float m = -1e30f;
        #pragma unroll
        for (int s = 0; s < NSPLIT; s++) {
            ms[s] = pm[(size_t)s*NROWS*NH + rh];
            ls[s] = pl[(size_t)s*NROWS*NH + rh];
            m = fmaxf(m, ms[s]);
        }
        float denom = 0.f;
        float w[NSPLIT];
        #pragma unroll
        for (int s = 0; s < NSPLIT; s++) {
            w[s] = __expf(ms[s] - m);
            denom += w[s] * ls[s];
        }
        float inv = 1.f / denom;
        size_t b0 = (size_t)row*ND + e;
        float v0 = 0.f, v1 = 0.f;
        #pragma unroll
        for (int s = 0; s < NSPLIT; s++) {
            size_t sb = (size_t)s*NROWS*ND + b0;
            v0 += w[s] * po[sb];
            v1 += w[s] * po[sb + 1];
        }
        v0 *= inv; v1 *= inv;
        split2(v0, v1, oh + b0, ol + b0);
    }
}

// ---------------- host orchestration ----------------
extern "C" void kernel_launch(void* const* d_in, const int* in_sizes, int n_in,
                              void* d_out, int out_size)
{
    (void)in_sizes; (void)n_in; (void)out_size;
    const int*   tgt = (const int*)d_in[0];
    const float* emb = (const float*)d_in[1];
    const float* Wq  = (const float*)d_in[2];
    const float* bq  = (const float*)d_in[3];
    const float* Wk  = (const float*)d_in[4];
    const float* bk  = (const float*)d_in[5];
    const float* Wv  = (const float*)d_in[6];
    const float* bv  = (const float*)d_in[7];
    const float* Wo  = (const float*)d_in[8];
    const float* bo  = (const float*)d_in[9];
    const float* rel = (const float*)d_in[10];
    const float* W1  = (const float*)d_in[11];
    const float* b1  = (const float*)d_in[12];
    const float* W2  = (const float*)d_in[13];
    const float* b2  = (const float*)d_in[14];
    const float* g1  = (const float*)d_in[15];
    const float* be1 = (const float*)d_in[16];
    const float* g2  = (const float*)d_in[17];
    const float* be2 = (const float*)d_in[18];
    const float* Wf  = (const float*)d_in[19];
    const float* bf  = (const float*)d_in[20];
    float* logits = (float*)d_out;

    float *x_, *qkv_, *p_, *bias3_, *po_, *pm_, *pl_;
    __nv_bfloat16 *qrb, *xh, *xl, *qh, *ql, *oh, *ol, *hh, *hl, *Bh, *Bl;
    cudaGetSymbolAddress((void**)&x_,    g_x);
    cudaGetSymbolAddress((void**)&qkv_,  g_qkv);
    cudaGetSymbolAddress((void**)&p_,    g_p);
    cudaGetSymbolAddress((void**)&bias3_, g_bias3);
    cudaGetSymbolAddress((void**)&po_,  g_po);
    cudaGetSymbolAddress((void**)&pm_,  g_pm);
    cudaGetSymbolAddress((void**)&pl_,  g_pl);
    cudaGetSymbolAddress((void**)&qrb, g_qrb);
    cudaGetSymbolAddress((void**)&xh,  g_xh);
    cudaGetSymbolAddress((void**)&xl,  g_xl);
    cudaGetSymbolAddress((void**)&qh,  g_qh);
    cudaGetSymbolAddress((void**)&ql,  g_ql);
    cudaGetSymbolAddress((void**)&oh,  g_oh);
    cudaGetSymbolAddress((void**)&ol,  g_ol);
    cudaGetSymbolAddress((void**)&hh,  g_hh);
    cudaGetSymbolAddress((void**)&hl,  g_hl);
    cudaGetSymbolAddress((void**)&Bh,  g_Bh);
    cudaGetSymbolAddress((void**)&Bl,  g_Bl);

    int attn_smem = (QT*LDQ + KT*LDQ + KT*LDQ + QT*LDQ)*(int)sizeof(float) + KT*(int)sizeof(int);
    cudaFuncSetAttribute(attn_kernel, cudaFuncAttributeMaxDynamicSharedMemorySize, attn_smem);
    cudaFuncSetAttribute(gemm_tc, cudaFuncAttributeMaxDynamicSharedMemorySize, GEMM_SMEM);

    embed_kernel<<<NROWS*ND/4/256, 256>>>(tgt, emb, x_, xh, xl);

    __nv_bfloat16* nb = nullptr;
    float* nf = nullptr;
    const int s4 = WDDE/4;              // float4s per DxD weight
    const int relq = NRQ*NDH/4;
    const int mgrid = (12*s4 + relq + 255)/256;

    for (int l = 0; l < NL; l++) {
        const size_t WDD = (size_t)WDDE;
        // one mega-split for all this layer's weights + rel
        megasplit_kernel<<<mgrid, 256>>>(
            reinterpret_cast<const float4*>(Wq + l*WDD),
            reinterpret_cast<const float4*>(Wk + l*WDD),
            reinterpret_cast<const float4*>(Wv + l*WDD),
            reinterpret_cast<const float4*>(Wo + l*WDD),
            reinterpret_cast<const float4*>(W1 + (size_t)l*NDFF*ND),
            reinterpret_cast<const float4*>(W2 + (size_t)l*ND*NDFF),
            reinterpret_cast<const float4*>(rel + (size_t)l*(2*NS-1)*NDH),
            Bh, Bl, s4, relq);
        concat3_kernel<<<12, 256>>>(bias3_, bq + l*ND, bk + l*ND, bv + l*ND);

        // fused QKV projection: N=3072, grid (24,16)
        gemm_tc<<<dim3(3*ND/128, NROWS/128), 256, GEMM_SMEM>>>(
            qkv_, qh, ql, xh, xl, Bh, Bl, bias3_, NROWS, 3*ND, ND, ND, ND, 1.f, 0, 3, 0);

        // QR: 1024 rel columns, triangular CTA skip, single-term bf16, hi-only out
        gemm_tc<<<dim3(NRQ/128, NROWS*NH/128), 256, GEMM_SMEM>>>(
            nf, qrb, nb, qh, ql, Bh + 12*WDD, Bl + 12*WDD, nf,
            NROWS*NH, NRQ, NRQ, NDH, NDH, 0.125f, 0, 1, 1);

        // attention: split-KV=4, then combine
        attn_kernel<<<dim3(NS/QT, NSPLIT, NB*NH), 128, attn_smem>>>(
            po_, pm_, pl_, qkv_, qrb, tgt);
        attn_combine<<<NROWS, 256>>>(oh, ol, po_, pm_, pl_);

        // output projection (split-K=2) + fused reduce+LN
        gemm_tc<<<dim3(ND/128, NROWS/128, 2), 256, GEMM_SMEM>>>(
            p_, nb, nb, oh, ol, Bh + 3*WDD, Bl + 3*WDD, nf,
            NROWS, ND, ND, 512, ND, 1.f, 0, 3, 0);
        red_ln_kernel<<<NROWS, 256>>>(x_, xh, xl, p_, bo + l*ND, g1 + l*ND, be1 + l*ND);

        // FFN1: write h directly as bf16 hi/lo
        gemm_tc<<<dim3(NDFF/128, NROWS/128), 256, GEMM_SMEM>>>(
            nf, hh, hl, xh, xl, Bh + 4*WDD, Bl + 4*WDD, b1 + l*NDFF,
            NROWS, NDFF, NDFF, ND, ND, 1.f, 1, 3, 0);
        // FFN2 (split-K=2) + fused reduce+LN
        gemm_tc<<<dim3(ND/128, NROWS/128, 2), 256, GEMM_SMEM>>>(
            p_, nb, nb, hh, hl, Bh + 8*WDD, Bl + 8*WDD, nf,
            NROWS, ND, ND, 2048, NDFF, 1.f, 0, 3, 0);
        red_ln_kernel<<<NROWS, 256>>>(x_, xh, xl, p_, b2 + l*ND, g2 + l*ND, be2 + l*ND);
    }

    // final logits: M=2048, N=32000, K=1024
    split_kernel<<<(int)((size_t)NV*ND/4 + 255)/256, 256>>>(
        reinterpret_cast<const float4*>(Wf), Bh, Bl, (int)((size_t)NV*ND/4));
    gemm_tc<<<dim3(NV/128, NROWS/128), 256, GEMM_SMEM>>>(
        logits, nb, nb, xh, xl, Bh, Bl, bf, NROWS, NV, NV, ND, ND, 1.f, 0, 3, 0);
}

// round 16
// speedup vs baseline: 1.2233x; 1.0359x over previous
#include <cuda_runtime.h>
#include <cuda_bf16.h>
#include <cstdint>
#include <math.h>

// ---------------- problem constants ----------------
#define NB 2
#define NS 1024
#define ND 1024
#define NH 16
#define NDH 64
#define NL 4
#define NDFF 4096
#define NV 32000
#define NRQ 1024             // qr columns actually used (rel idx 0..1023)
#define NROWS (NB*NS)        // 2048
#define NSPLIT 8             // attention split-KV factor
#define KVSEG (NS/NSPLIT)    // 128
#define WDDE (ND*ND)         // 1M elements per DxD weight

// ---------------- scratch (static device allocations) ----------------
__device__ float g_x[NROWS*ND];
__device__ float g_qkv[NROWS*3*ND];                   // fused q|k|v, stride 3072
__device__ float g_p[2*NROWS*ND];                     // split-K partials
__device__ float g_bias3[3*ND];
__device__ __nv_bfloat16 g_qrb[(size_t)NROWS*NH*NRQ]; // qr in bf16 (1024 cols)
// attention split-KV partials
__device__ float g_po[(size_t)NSPLIT*NROWS*ND];
__device__ float g_pm[NSPLIT*NROWS*NH];
__device__ float g_pl[NSPLIT*NROWS*NH];

// split-bf16 activation buffers (hi/lo)
__device__ __nv_bfloat16 g_xh[NROWS*ND],  g_xl[NROWS*ND];
__device__ __nv_bfloat16 g_qh[NROWS*ND],  g_ql[NROWS*ND];
__device__ __nv_bfloat16 g_oh[NROWS*ND],  g_ol[NROWS*ND];
__device__ __nv_bfloat16 g_hh[NROWS*NDFF], g_hl[NROWS*NDFF];
// weight split buffers (layer layout: QKV[0,3W) Wo[3W,4W) W1[4W,8W) W2[8W,12W) rel[12W,+64K))
__device__ __nv_bfloat16 g_Bh[(size_t)NV*ND];
__device__ __nv_bfloat16 g_Bl[(size_t)NV*ND];

// ---------------- helpers ----------------
__device__ __forceinline__ uint32_t smem_u32(const void* p) {
    uint32_t a;
    asm("{ .reg .u64 t; cvta.to.shared.u64 t, %1; cvt.u32.u64 %0, t; }" : "=r"(a) : "l"(p));
    return a;
}

#define LDSM4(r, a) \
    asm volatile("ldmatrix.sync.aligned.m8n8.x4.shared.b16 {%0,%1,%2,%3}, [%4];" \
        : "=r"((r)[0]), "=r"((r)[1]), "=r"((r)[2]), "=r"((r)[3]) : "r"(a))
#define LDSM2(r, a) \
    asm volatile("ldmatrix.sync.aligned.m8n8.x2.shared.b16 {%0,%1}, [%2];" \
        : "=r"((r)[0]), "=r"((r)[1]) : "r"(a))

#define MMA16816(d, a, b) \
    asm volatile("mma.sync.aligned.m16n8k16.row.col.f32.bf16.bf16.f32 " \
        "{%0,%1,%2,%3}, {%4,%5,%6,%7}, {%8,%9}, {%0,%1,%2,%3};" \
        : "+f"((d)[0]), "+f"((d)[1]), "+f"((d)[2]), "+f"((d)[3]) \
        : "r"((a)[0]), "r"((a)[1]), "r"((a)[2]), "r"((a)[3]), "r"((b)[0]), "r"((b)[1]))

#define CP_ASYNC16(dst, src, sz) \
    asm volatile("cp.async.cg.shared.global [%0], [%1], 16, %2;" \
        :: "r"(dst), "l"(src), "r"(sz))
#define CP_COMMIT() asm volatile("cp.async.commit_group;")
#define CP_WAIT0()  asm volatile("cp.async.wait_group 0;")
#define CP_WAIT1()  asm volatile("cp.async.wait_group 1;")

__device__ __forceinline__ void split2(float v0, float v1,
                                       __nv_bfloat16* hi, __nv_bfloat16* lo) {
    __nv_bfloat16 h0 = __float2bfloat16(v0);
    __nv_bfloat16 h1 = __float2bfloat16(v1);
    __nv_bfloat16 l0 = __float2bfloat16(v0 - __bfloat162float(h0));
    __nv_bfloat16 l1 = __float2bfloat16(v1 - __bfloat162float(h1));
    *reinterpret_cast<__nv_bfloat162*>(hi) = __nv_bfloat162(h0, h1);
    *reinterpret_cast<__nv_bfloat162*>(lo) = __nv_bfloat162(l0, l1);
}

// ---------------- fp32 -> bf16 hi/lo split (single source; used for Wf) ----------------
__global__ void split_kernel(const float4* __restrict__ src,
                             __nv_bfloat16* __restrict__ hi,
                             __nv_bfloat16* __restrict__ lo, int n4) {
    int i = blockIdx.x * 256 + threadIdx.x;
    if (i >= n4) return;
    float4 v = src[i];
    split2(v.x, v.y, hi + i*4,     lo + i*4);
    split2(v.z, v.w, hi + i*4 + 2, lo + i*4 + 2);
}

// ---------------- per-layer mega split: QKV | Wo | W1 | W2 | rel + bias concat ----------------
// s = WDDE/4 float4 units per DxD weight; relq = NRQ*NDH/4; tail 768 float4 = bias concat.
__global__ void megasplit_kernel(
    const float4* __restrict__ wq, const float4* __restrict__ wk,
    const float4* __restrict__ wv, const float4* __restrict__ wo,
    const float4* __restrict__ w1, const float4* __restrict__ w2,
    const float4* __restrict__ rl,
    const float4* __restrict__ ba, const float4* __restrict__ bb,
    const float4* __restrict__ bc, float4* __restrict__ bias3,
    __nv_bfloat16* __restrict__ hi, __nv_bfloat16* __restrict__ lo,
    int s, int relq)
{
    int i = blockIdx.x * 256 + threadIdx.x;
    int nsplit = 12*s + relq;
    if (i >= nsplit) {
        int t = i - nsplit;           // bias concat: 3*ND/4 = 768 float4
        if (t < 3*ND/4) {
            const float4* src = (t < ND/4) ? ba : (t < ND/2 ? bb : bc);
            int j = (t < ND/4) ? t : (t < ND/2 ? t - ND/4 : t - ND/2);
            bias3[t] = src[j];
        }
        return;
    }
    const float4* src;
    int j;
    if (i < 3*s) {
        if (i < s)        { src = wq; j = i; }
        else if (i < 2*s) { src = wk; j = i - s; }
        else              { src = wv; j = i - 2*s; }
    } else if (i < 4*s)   { src = wo; j = i - 3*s; }
    else if (i < 8*s)     { src = w1; j = i - 4*s; }
    else if (i < 12*s)    { src = w2; j = i - 8*s; }
    else                  { src = rl; j = i - 12*s; }
    float4 v = src[j];
    split2(v.x, v.y, hi + (size_t)i*4,     lo + (size_t)i*4);
    split2(v.z, v.w, hi + (size_t)i*4 + 2, lo + (size_t)i*4 + 2);
}

// ---------------- embedding: x = emb[tgt]*32, also emit hi/lo ----------------
__global__ void embed_kernel(const int* __restrict__ tgt,
                             const float* __restrict__ emb,
                             float* __restrict__ x,
                             __nv_bfloat16* __restrict__ xh,
                             __nv_bfloat16* __restrict__ xl) {
    int idx = blockIdx.x * blockDim.x + threadIdx.x;
    int row = idx >> 8;
    int c4  = idx & 255;
    float4 v = reinterpret_cast<const float4*>(emb + (size_t)tgt[row] * ND)[c4];
    v.x *= 32.f; v.y *= 32.f; v.z *= 32.f; v.w *= 32.f;
    reinterpret_cast<float4*>(x)[idx] = v;
    split2(v.x, v.y, xh + idx*4,     xl + idx*4);
    split2(v.z, v.w, xh + idx*4 + 2, xl + idx*4 + 2);
}

// ---------------- fused split-K reduce + residual + LayerNorm ----------------
__global__ __launch_bounds__(256) void red_ln_kernel(
    float* __restrict__ x, __nv_bfloat16* __restrict__ xh, __nv_bfloat16* __restrict__ xl,
    const float* __restrict__ P, const float* __restrict__ bias,
    const float* __restrict__ gw, const float* __restrict__ bw)
{
    __shared__ float buf[ND];
    __shared__ float red[33];
    int row = blockIdx.x;
    int tid = threadIdx.x;
    size_t base = (size_t)row * ND;
    const float* P0 = P + base;
    const float* P1 = P + (size_t)NROWS*ND + base;

    float s = 0.f;
    for (int d = tid; d < ND; d += 256) {
        float t = x[base + d] + P0[d] + P1[d] + bias[d];
        buf[d] = t;
        s += t;
    }
    #pragma unroll
    for (int off = 16; off; off >>= 1) s += __shfl_xor_sync(0xffffffffu, s, off);
    if ((tid & 31) == 0) red[tid >> 5] = s;
    __syncthreads();
    if (tid < 32) {
        float v2 = (tid < 8) ? red[tid] : 0.f;
        #pragma unroll
        for (int off = 4; off; off >>= 1) v2 += __shfl_xor_sync(0xffffffffu, v2, off);
        if (tid == 0) red[32] = v2;
    }
    __syncthreads();
    float mean = red[32] * (1.f/ND);

    float sv = 0.f;
    for (int d = tid; d < ND; d += 256) {
        float t = buf[d] - mean;
        sv += t*t;
    }
    #pragma unroll
    for (int off = 16; off; off >>= 1) sv += __shfl_xor_sync(0xffffffffu, sv, off);
    __syncthreads();
    if ((tid & 31) == 0) red[tid >> 5] = sv;
    __syncthreads();
    if (tid < 32) {
        float v2 = (tid < 8) ? red[tid] : 0.f;
        #pragma unroll
        for (int off = 4; off; off >>= 1) v2 += __shfl_xor_sync(0xffffffffu, v2, off);
        if (tid == 0) red[32] = v2;
    }
    __syncthreads();
    float inv = rsqrtf(red[32] * (1.f/ND) + 1e-5f);
    for (int d = tid*2; d < ND; d += 512) {
        float v0 = (buf[d]   - mean) * inv * gw[d]   + bw[d];
        float v1 = (buf[d+1] - mean) * inv * gw[d+1] + bw[d+1];
        x[base + d]   = v0;
        x[base + d+1] = v1;
        split2(v0, v1, xh + base + d, xl + base + d);
    }
}

// ---------------- split-bf16 tensor-core GEMM (mma.sync) ----------------
#define STG 32768
#define TOFF 8192
#define GEMM_SMEM (3*STG)

__device__ __forceinline__ void ld_tile_async(
    uint32_t sbase, const __nv_bfloat16* __restrict__ g,
    int ldk, int row0, int k0, int rmax, int tid)
{
    #pragma unroll
    for (int it = 0; it < 2; it++) {
        int qq = tid + it * 256;
        int r = qq >> 2, c = qq & 3;
        uint32_t dst = sbase + r * 64 + ((c ^ ((r >> 1) & 3)) << 4);
        int rr = (r < rmax) ? r : 0;
        const __nv_bfloat16* src = g + (size_t)(row0 + rr) * ldk + k0 + c * 8;
        int sz = (r < rmax) ? 16 : 0;
        CP_ASYNC16(dst, src, sz);
    }
}

__device__ __forceinline__ void ld_stage(
    uint32_t sbase, const __nv_bfloat16* Ah, const __nv_bfloat16* Al,
    const __nv_bfloat16* Bh, const __nv_bfloat16* Bl,
    int ldk, int m0, int n0, int k0, int bn, int tid, int terms)
{
    ld_tile_async(sbase + 0*TOFF, Ah, ldk, m0, k0, 128, tid);
    ld_tile_async(sbase + 2*TOFF, Bh, ldk, n0, k0, bn, tid);
    if (terms == 3) {
        ld_tile_async(sbase + 1*TOFF, Al, ldk, m0, k0, 128, tid);
        ld_tile_async(sbase + 3*TOFF, Bl, ldk, n0, k0, bn, tid);
    }
}

__global__ __launch_bounds__(256, 2) void gemm_tc(
    float* __restrict__ C, __nv_bfloat16* __restrict__ Ch, __nv_bfloat16* __restrict__ Cl,
    const __nv_bfloat16* __restrict__ Ah, const __nv_bfloat16* __restrict__ Al,
    const __nv_bfloat16* __restrict__ Bh, const __nv_bfloat16* __restrict__ Bl,
    const float* __restrict__ bias, int M, int N, int Nh, int K, int ldk,
    float alpha, int relu, int terms, int tri)
{
    extern __shared__ char sm[];
    uint32_t smb = smem_u32(sm);
    int tid = threadIdx.x;
    int wid = tid >> 5;
    int lane = tid & 31;
    int wm = wid & 1;
    int wn = wid >> 1;
    int m0 = blockIdx.y * 128;
    int n0 = blockIdx.x * 128;

    // triangular skip (QR): rows m0..m0+127 encode i = (row>>4) mod 1024;
    // column block dead iff n0+127 < 1016 - i_min.
    if (tri) {
        int imin = (m0 >> 4) & (NS - 1);
        if (n0 + 127 < 1016 - imin) return;
    }

    int kbase = blockIdx.z * K;
    if (C) C += (size_t)blockIdx.z * M * N;
    int NT = K >> 5;
    int bn = N - n0; if (bn > 128) bn = 128;

    ld_stage(smb, Ah, Al, Bh, Bl, ldk, m0, n0, kbase, bn, tid, terms);
    CP_COMMIT();
    if (NT > 1) {
        ld_stage(smb + STG, Ah, Al, Bh, Bl, ldk, m0, n0, kbase + 32, bn, tid, terms);
        CP_COMMIT();
    }

    float acc[4][4][4];
    #pragma unroll
    for (int i = 0; i < 4; i++)
        #pragma unroll
        for (int j = 0; j < 4; j++)
            #pragma unroll
            for (int e = 0; e < 4; e++) acc[i][j][e] = 0.f;

    int slot = 0, pslot = 2;
    for (int kt = 0; kt < NT; kt++) {
        if (kt + 1 < NT) { CP_WAIT1(); } else { CP_WAIT0(); }
        __syncthreads();

        if (kt + 2 < NT) {
            ld_stage(smb + pslot * STG, Ah, Al, Bh, Bl, ldk, m0, n0,
                     kbase + ((kt + 2) << 5), bn, tid, terms);
            CP_COMMIT();
        }

        uint32_t sA = smb + slot * STG;
        uint32_t sB = sA + 2*TOFF;

        #pragma unroll
        for (int ks = 0; ks < 2; ks++) {
            uint32_t ah[4][4], al[4][4], bh[4][2], bl[4][2];
            #pragma unroll
            for (int mf = 0; mf < 4; mf++) {
                int row = wm * 64 + mf * 16 + (lane & 15);
                int cc = ks * 2 + (lane >> 4);
                uint32_t ad = sA + row * 64 + (((cc ^ ((row >> 1) & 3))) << 4);
                LDSM4(ah[mf], ad);
                if (terms == 3) LDSM4(al[mf], ad + TOFF);
            }
            #pragma unroll
            for (int nf = 0; nf < 4; nf++) {
                int rn = wn * 32 + nf * 8 + (lane & 7);
                int cc = ks * 2 + ((lane >> 3) & 1);
                uint32_t bd = sB + rn * 64 + (((cc ^ ((rn >> 1) & 3))) << 4);
                LDSM2(bh[nf], bd);
                if (terms == 3) LDSM2(bl[nf], bd + TOFF);
            }
            #pragma unroll
            for (int mf = 0; mf < 4; mf++)
                #pragma unroll
                for (int nf = 0; nf < 4; nf++)
                    MMA16816(acc[mf][nf], ah[mf], bh[nf]);
            if (terms == 3) {
                #pragma unroll
                for (int mf = 0; mf < 4; mf++)
                    #pragma unroll
                    for (int nf = 0; nf < 4; nf++)
                        MMA16816(acc[mf][nf], ah[mf], bl[nf]);
                #pragma unroll
                for (int mf = 0; mf < 4; mf++)
                    #pragma unroll
                    for (int nf = 0; nf < 4; nf++)
                        MMA16816(acc[mf][nf], al[mf], bh[nf]);
            }
        }
        slot = (slot == 2) ? 0 : slot + 1;
        pslot = (pslot == 2) ? 0 : pslot + 1;
    }

    // epilogue: vector paths require even row strides (alignment!)
    bool fastC  = (C != nullptr)  && ((N & 1) == 0)  && (n0 + 128 <= N);
    bool fastCh = (Ch != nullptr) && ((Nh & 1) == 0) && (n0 + 128 <= Nh);
    #pragma unroll
    for (int mf = 0; mf < 4; mf++) {
        int r0 = m0 + wm * 64 + mf * 16 + (lane >> 2);
        #pragma unroll
        for (int half = 0; half < 2; half++) {
            int row = r0 + half * 8;
            size_t rbase = (size_t)row * N;
            size_t rbh   = (size_t)row * Nh;
            #pragma unroll
            for (int nf = 0; nf < 4; nf++) {
                int col = n0 + wn * 32 + nf * 8 + (lane & 3) * 2;
                float v0 = acc[mf][nf][half * 2 + 0];
                float v1 = acc[mf][nf][half * 2 + 1];
                if (bias) { v0 += bias[col]; v1 += __ldg(&bias[col + 1]); }
                v0 *= alpha; v1 *= alpha;
                if (relu) { v0 = fmaxf(v0, 0.f); v1 = fmaxf(v1, 0.f); }
                if (fastC) {
                    *reinterpret_cast<float2*>(C + rbase + col) = make_float2(v0, v1);
                } else if (C) {
                    if (col < N)     C[rbase + col] = v0;
                    if (col + 1 < N) C[rbase + col + 1] = v1;
                }
                if (fastCh) {
                    if (Cl) split2(v0, v1, Ch + rbh + col, Cl + rbh + col);
                    else *reinterpret_cast<__nv_bfloat162*>(Ch + rbh + col) =
                             __nv_bfloat162(__float2bfloat16(v0), __float2bfloat16(v1));
                } else if (Ch) {
                    if (col < Nh)     Ch[rbh + col] = __float2bfloat16(v0);
                    if (col + 1 < Nh) Ch[rbh + col + 1] = __float2bfloat16(v1);
                }
            }
        }
    }
}

// ---------------- fused attention, split-KV=8 (flash partials) ----------------
#define QT 128
#define KT 64
#define LDQ 68
#define QKVS (3*ND)

__global__ __launch_bounds__(128, 2) void attn_kernel(
    float* __restrict__ po, float* __restrict__ pm, float* __restrict__ pl,
    const float* __restrict__ qkv, const __nv_bfloat16* __restrict__ qrb,
    const int* __restrict__ tgt)
{
    extern __shared__ float smf[];
    float* qs = smf;
    float* ks = qs + QT*LDQ;
    float* vs = ks + KT*LDQ;
    float* ps = vs + KT*LDQ;
    int*   pf = (int*)(ps + QT*LDQ);

    int split = blockIdx.y;
    int bh = blockIdx.z;
    int b = bh >> 4, h = bh & 15;
    int tid = threadIdx.x;
    int i0 = blockIdx.x * QT;
    int i  = i0 + tid;

    int jend = (tgt[b*NS] == 0) ? NS : (i0 + QT);
    int jstart = split * KVSEG;
    int jstop  = (jend < (split + 1) * KVSEG) ? jend : (split + 1) * KVSEG;

    size_t rh = (size_t)(b*NS + i)*NH + h + (size_t)split*NROWS*NH;

    if (jstart >= jstop) {
        // empty segment: neutral (m,l); po left stale (weighted by exactly 0)
        pm[rh] = -1e30f;
        pl[rh] = 0.f;
        return;
    }

    float o[NDH];
    #pragma unroll
    for (int d = 0; d < NDH; d++) o[d] = 0.f;
    float m = -1e30f, l = 0.f;

    for (int t = tid; t < QT*NDH/4; t += 128) {
        int r  = t >> 4;
        int c4 = (t & 15) << 2;
        float4 va = *reinterpret_cast<const float4*>(
            &qkv[((size_t)(b*NS + i0 + r))*QKVS + h*NDH + c4]);
        va.x *= 0.125f; va.y *= 0.125f; va.z *= 0.125f; va.w *= 0.125f;
        *reinterpret_cast<float4*>(&qs[r*LDQ + c4]) = va;
    }

    const __nv_bfloat16* qrrow =
        qrb + ((size_t)((b*NS + i)*NH + h)) * NRQ + (1023 - i);

    for (int j0 = jstart; j0 < jstop; j0 += KT) {
        __syncthreads();
        for (int t = tid; t < KT*NDH/4; t += 128) {
            int r  = t >> 4;
            int c4 = (t & 15) << 2;
            size_t g = ((size_t)(b*NS + j0 + r))*QKVS + h*NDH + c4;
            *reinterpret_cast<float4*>(&ks[r*LDQ + c4]) =
                *reinterpret_cast<const float4*>(&qkv[g + ND]);
            *reinterpret_cast<float4*>(&vs[r*LDQ + c4]) =
                *reinterpret_cast<const float4*>(&qkv[g + 2*ND]);
        }
        if (tid < KT) pf[tid] = (tgt[b*NS + j0 + tid] == 0) ? 1 : 0;
        __syncthreads();

        float s[KT];
        #pragma unroll
        for (int j = 0; j < KT; j++) s[j] = 0.f;
        #pragma unroll 1
        for (int d = 0; d < NDH; d += 4) {
            float4 qd = *reinterpret_cast<const float4*>(&qs[tid*LDQ + d]);
            #pragma unroll
            for (int j = 0; j < KT; j++) {
                float4 kj = *reinterpret_cast<const float4*>(&ks[j*LDQ + d]);
                s[j] += qd.x*kj.x + qd.y*kj.y + qd.z*kj.z + qd.w*kj.w;
            }
        }
        float mt = m;
        #pragma unroll
        for (int j = 0; j < KT; j++) {
            int jj = j0 + j;
            float val;
            if (jj > i || pf[j]) val = -1e9f;
            else val = s[j] + __bfloat162float(qrrow[jj]);
            s[j] = val;
            mt = fmaxf(mt, val);
        }
        float corr = __expf(m - mt);
        m = mt;
        l *= corr;
        #pragma unroll
        for (int d = 0; d < NDH; d++) o[d] *= corr;
        #pragma unroll
        for (int j = 0; j < KT; j += 4) {
            float4 pv;
            pv.x = __expf(s[j]   - m);
            pv.y = __expf(s[j+1] - m);
            pv.z = __expf(s[j+2] - m);
            pv.w = __expf(s[j+3] - m);
            l += pv.x + pv.y + pv.z + pv.w;
            *reinterpret_cast<float4*>(&ps[tid*LDQ + j]) = pv;
        }
        #pragma unroll 1
        for (int j = 0; j < KT; j++) {
            float p = ps[tid*LDQ + j];
            #pragma unroll
            for (int d = 0; d < NDH; d += 4) {
                float4 vj = *reinterpret_cast<const float4*>(&vs[j*LDQ + d]);
                o[d]   += p*vj.x;
                o[d+1] += p*vj.y;
                o[d+2] += p*vj.z;
                o[d+3] += p*vj.w;
            }
        }
    }

    pm[rh] = m;
    pl[rh] = l;
    size_t ob = (size_t)split*NROWS*ND + ((size_t)(b*NS + i))*ND + h*NDH;
    #pragma unroll
    for (int d = 0; d < NDH; d += 4)
        *reinterpret_cast<float4*>(&po[ob + d]) = make_float4(o[d], o[d+1], o[d+2], o[d+3]);
}

// ---------------- attention combine: merge NSPLIT partials -> bf16 hi/lo ----------------
__global__ __launch_bounds__(256) void attn_combine(
    __nv_bfloat16* __restrict__ oh, __nv_bfloat16* __restrict__ ol,
    const float* __restrict__ po, const float* __restrict__ pm, const float* __restrict__ pl)
{
    int row = blockIdx.x;
    int tid = threadIdx.x;
    for (int e = tid*2; e < ND; e += 512) {
        int h = e >> 6;
        size_t rh = (size_t)row*NH + h;
        float ms[NSPLIT], ls[NSPLIT];
        float m = -1e30f;
        #pragma unroll
        for (int s = 0; s < NSPLIT; s++) {
            ms[s] = pm[(size_t)s*NROWS*NH + rh];
            ls[s] = pl[(size_t)s*NROWS*NH + rh];
            m = fmaxf(m, ms[s]);
        }
        float denom = 0.f;
        float w[NSPLIT];
        #pragma unroll
        for (int s = 0; s < NSPLIT; s++) {
            w[s] = __expf(ms[s] - m);
            denom += w[s] * ls[s];
        }
        float inv = 1.f / denom;
        size_t b0 = (size_t)row*ND + e;
        float v0 = 0.f, v1 = 0.f;
        #pragma unroll
        for (int s = 0; s < NSPLIT; s++) {
            if (w[s] > 0.f) {
                size_t sb = (size_t)s*NROWS*ND + b0;
                v0 += w[s] * po[sb];
                v1 += w[s] * po[sb + 1];
            }
        }
        v0 *= inv; v1 *= inv;
        split2(v0, v1, oh + b0, ol + b0);
    }
}

// ---------------- host orchestration ----------------
extern "C" void kernel_launch(void* const* d_in, const int* in_sizes, int n_in,
                              void* d_out, int out_size)
{
    (void)in_sizes; (void)n_in; (void)out_size;
    const int*   tgt = (const int*)d_in[0];
    const float* emb = (const float*)d_in[1];
    const float* Wq  = (const float*)d_in[2];
    const float* bq  = (const float*)d_in[3];
    const float* Wk  = (const float*)d_in[4];
    const float* bk  = (const float*)d_in[5];
    const float* Wv  = (const float*)d_in[6];
    const float* bv  = (const float*)d_in[7];
    const float* Wo  = (const float*)d_in[8];
    const float* bo  = (const float*)d_in[9];
    const float* rel = (const float*)d_in[10];
    const float* W1  = (const float*)d_in[11];
    const float* b1  = (const float*)d_in[12];
    const float* W2  = (const float*)d_in[13];
    const float* b2  = (const float*)d_in[14];
    const float* g1  = (const float*)d_in[15];
    const float* be1 = (const float*)d_in[16];
    const float* g2  = (const float*)d_in[17];
    const float* be2 = (const float*)d_in[18];
    const float* Wf  = (const float*)d_in[19];
    const float* bf  = (const float*)d_in[20];
    float* logits = (float*)d_out;

    float *x_, *qkv_, *p_, *bias3_, *po_, *pm_, *pl_;
    __nv_bfloat16 *qrb, *xh, *xl, *qh, *ql, *oh, *ol, *hh, *hl, *Bh, *Bl;
    cudaGetSymbolAddress((void**)&x_,    g_x);
    cudaGetSymbolAddress((void**)&qkv_,  g_qkv);
    cudaGetSymbolAddress((void**)&p_,    g_p);
    cudaGetSymbolAddress((void**)&bias3_, g_bias3);
    cudaGetSymbolAddress((void**)&po_,  g_po);
    cudaGetSymbolAddress((void**)&pm_,  g_pm);
    cudaGetSymbolAddress((void**)&pl_,  g_pl);
    cudaGetSymbolAddress((void**)&qrb, g_qrb);
    cudaGetSymbolAddress((void**)&xh,  g_xh);
    cudaGetSymbolAddress((void**)&xl,  g_xl);
    cudaGetSymbolAddress((void**)&qh,  g_qh);
    cudaGetSymbolAddress((void**)&ql,  g_ql);
    cudaGetSymbolAddress((void**)&oh,  g_oh);
    cudaGetSymbolAddress((void**)&ol,  g_ol);
    cudaGetSymbolAddress((void**)&hh,  g_hh);
    cudaGetSymbolAddress((void**)&hl,  g_hl);
    cudaGetSymbolAddress((void**)&Bh,  g_Bh);
    cudaGetSymbolAddress((void**)&Bl,  g_Bl);

    int attn_smem = (QT*LDQ + KT*LDQ + KT*LDQ + QT*LDQ)*(int)sizeof(float) + KT*(int)sizeof(int);
    cudaFuncSetAttribute(attn_kernel, cudaFuncAttributeMaxDynamicSharedMemorySize, attn_smem);
    cudaFuncSetAttribute(gemm_tc, cudaFuncAttributeMaxDynamicSharedMemorySize, GEMM_SMEM);

    embed_kernel<<<NROWS*ND/4/256, 256>>>(tgt, emb, x_, xh, xl);

    __nv_bfloat16* nb = nullptr;
    float* nf = nullptr;
    const int s4 = WDDE/4;              // float4s per DxD weight
    const int relq = NRQ*NDH/4;
    const int mgrid = (12*s4 + relq + 3*ND/4 + 255)/256;

    for (int l = 0; l < NL; l++) {
        const size_t WDD = (size_t)WDDE;
        // one mega-split for all this layer's weights + rel + bias concat
        megasplit_kernel<<<mgrid, 256>>>(
            reinterpret_cast<const float4*>(Wq + l*WDD),
            reinterpret_cast<const float4*>(Wk + l*WDD),
            reinterpret_cast<const float4*>(Wv + l*WDD),
            reinterpret_cast<const float4*>(Wo + l*WDD),
            reinterpret_cast<const float4*>(W1 + (size_t)l*NDFF*ND),
            reinterpret_cast<const float4*>(W2 + (size_t)l*ND*NDFF),
            reinterpret_cast<const float4*>(rel + (size_t)l*(2*NS-1)*NDH),
            reinterpret_cast<const float4*>(bq + l*ND),
            reinterpret_cast<const float4*>(bk + l*ND),
            reinterpret_cast<const float4*>(bv + l*ND),
            reinterpret_cast<float4*>(bias3_),
            Bh, Bl, s4, relq);

        // fused QKV projection: N=3072, grid (24,16)
        gemm_tc<<<dim3(3*ND/128, NROWS/128), 256, GEMM_SMEM>>>(
            qkv_, qh, ql, xh, xl, Bh, Bl, bias3_, NROWS, 3*ND, ND, ND, ND, 1.f, 0, 3, 0);

        // QR: 1024 rel columns, triangular CTA skip, single-term bf16, hi-only out
        gemm_tc<<<dim3(NRQ/128, NROWS*NH/128), 256, GEMM_SMEM>>>(
            nf, qrb, nb, qh, ql, Bh + 12*WDD, Bl + 12*WDD, nf,
            NROWS*NH, NRQ, NRQ, NDH, NDH, 0.125f, 0, 1, 1);

        // attention: split-KV=8, then combine
        attn_kernel<<<dim3(NS/QT, NSPLIT, NB*NH), 128, attn_smem>>>(
            po_, pm_, pl_, qkv_, qrb, tgt);
        attn_combine<<<NROWS, 256>>>(oh, ol, po_, pm_, pl_);

        // output projection (split-K=2) + fused reduce+LN
        gemm_tc<<<dim3(ND/128, NROWS/128, 2), 256, GEMM_SMEM>>>(
            p_, nb, nb, oh, ol, Bh + 3*WDD, Bl + 3*WDD, nf,
            NROWS, ND, ND, 512, ND, 1.f, 0, 3, 0);
        red_ln_kernel<<<NROWS, 256>>>(x_, xh, xl, p_, bo + l*ND, g1 + l*ND, be1 + l*ND);

        // FFN1: write h directly as bf16 hi/lo
        gemm_tc<<<dim3(NDFF/128, NROWS/128), 256, GEMM_SMEM>>>(
            nf, hh, hl, xh, xl, Bh + 4*WDD, Bl + 4*WDD, b1 + l*NDFF,
            NROWS, NDFF, NDFF, ND, ND, 1.f, 1, 3, 0);
        // FFN2 (split-K=2) + fused reduce+LN
        gemm_tc<<<dim3(ND/128, NROWS/128, 2), 256, GEMM_SMEM>>>(
            p_, nb, nb, hh, hl, Bh + 8*WDD, Bl + 8*WDD, nf,
            NROWS, ND, ND, 2048, NDFF, 1.f, 0, 3, 0);
        red_ln_kernel<<<NROWS, 256>>>(x_, xh, xl, p_, b2 + l*ND, g2 + l*ND, be2 + l*ND);
    }

    // final logits: M=2048, N=32000, K=1024
    split_kernel<<<(int)((size_t)NV*ND/4 + 255)/256, 256>>>(
        reinterpret_cast<const float4*>(Wf), Bh, Bl, (int)((size_t)NV*ND/4));
    gemm_tc<<<dim3(NV/128, NROWS/128), 256, GEMM_SMEM>>>(
        logits, nb, nb, xh, xl, Bh, Bl, bf, NROWS, NV, NV, ND, ND, 1.f, 0, 3, 0);
}

// round 17
// speedup vs baseline: 1.2304x; 1.0058x over previous
#include <cuda_runtime.h>
#include <cuda_bf16.h>
#include <cstdint>
#include <math.h>

// ---------------- problem constants ----------------
#define NB 2
#define NS 1024
#define ND 1024
#define NH 16
#define NDH 64
#define NL 4
#define NDFF 4096
#define NV 32000
#define NRQ 1024             // qr columns actually used (rel idx 0..1023)
#define NROWS (NB*NS)        // 2048
#define NSPLIT 8             // attention split-KV factor
#define KVSEG (NS/NSPLIT)    // 128
#define WDDE (ND*ND)         // 1M elements per DxD weight
#define LOFF (13*1024*1024)  // per-layer weight buffer stride (elements)

// ---------------- scratch (static device allocations) ----------------
__device__ float g_x[NROWS*ND];
__device__ float g_qkv[NROWS*3*ND];                   // fused q|k|v, stride 3072
__device__ float g_p[2*NROWS*ND];                     // split-K partials
__device__ float g_bias3[2*3*ND];                     // double-buffered
__device__ __nv_bfloat16 g_qrb[(size_t)NROWS*NH*NRQ]; // qr in bf16 (1024 cols)
// attention split-KV partials
__device__ float g_po[(size_t)NSPLIT*NROWS*ND];
__device__ float g_pm[NSPLIT*NROWS*NH];
__device__ float g_pl[NSPLIT*NROWS*NH];

// split-bf16 activation buffers (hi/lo)
__device__ __nv_bfloat16 g_xh[NROWS*ND],  g_xl[NROWS*ND];
__device__ __nv_bfloat16 g_qh[NROWS*ND],  g_ql[NROWS*ND];
__device__ __nv_bfloat16 g_oh[NROWS*ND],  g_ol[NROWS*ND];
__device__ __nv_bfloat16 g_hh[NROWS*NDFF], g_hl[NROWS*NDFF];
// layer weight split buffers, double-buffered at stride LOFF
// (per layer: QKV[0,3W) Wo[3W,4W) W1[4W,8W) W2[8W,12W) rel[12W,+64K))
__device__ __nv_bfloat16 g_Bh[(size_t)NV*ND];
__device__ __nv_bfloat16 g_Bl[(size_t)NV*ND];
// dedicated Wf split buffers
__device__ __nv_bfloat16 g_Wfh[(size_t)NV*ND];
__device__ __nv_bfloat16 g_Wfl[(size_t)NV*ND];

// ---------------- helpers ----------------
__device__ __forceinline__ uint32_t smem_u32(const void* p) {
    uint32_t a;
    asm("{ .reg .u64 t; cvta.to.shared.u64 t, %1; cvt.u32.u64 %0, t; }" : "=r"(a) : "l"(p));
    return a;
}

#define LDSM4(r, a) \
    asm volatile("ldmatrix.sync.aligned.m8n8.x4.shared.b16 {%0,%1,%2,%3}, [%4];" \
        : "=r"((r)[0]), "=r"((r)[1]), "=r"((r)[2]), "=r"((r)[3]) : "r"(a))
#define LDSM2(r, a) \
    asm volatile("ldmatrix.sync.aligned.m8n8.x2.shared.b16 {%0,%1}, [%2];" \
        : "=r"((r)[0]), "=r"((r)[1]) : "r"(a))

#define MMA16816(d, a, b) \
    asm volatile("mma.sync.aligned.m16n8k16.row.col.f32.bf16.bf16.f32 " \
        "{%0,%1,%2,%3}, {%4,%5,%6,%7}, {%8,%9}, {%0,%1,%2,%3};" \
        : "+f"((d)[0]), "+f"((d)[1]), "+f"((d)[2]), "+f"((d)[3]) \
        : "r"((a)[0]), "r"((a)[1]), "r"((a)[2]), "r"((a)[3]), "r"((b)[0]), "r"((b)[1]))

#define CP_ASYNC16(dst, src, sz) \
    asm volatile("cp.async.cg.shared.global [%0], [%1], 16, %2;" \
        :: "r"(dst), "l"(src), "r"(sz))
#define CP_COMMIT() asm volatile("cp.async.commit_group;")
#define CP_WAIT0()  asm volatile("cp.async.wait_group 0;")
#define CP_WAIT1()  asm volatile("cp.async.wait_group 1;")

__device__ __forceinline__ void split2(float v0, float v1,
                                       __nv_bfloat16* hi, __nv_bfloat16* lo) {
    __nv_bfloat16 h0 = __float2bfloat16(v0);
    __nv_bfloat16 h1 = __float2bfloat16(v1);
    __nv_bfloat16 l0 = __float2bfloat16(v0 - __bfloat162float(h0));
    __nv_bfloat16 l1 = __float2bfloat16(v1 - __bfloat162float(h1));
    *reinterpret_cast<__nv_bfloat162*>(hi) = __nv_bfloat162(h0, h1);
    *reinterpret_cast<__nv_bfloat162*>(lo) = __nv_bfloat162(l0, l1);
}

// ---------------- fp32 -> bf16 hi/lo split (single source; used for Wf) ----------------
__global__ void split_kernel(const float4* __restrict__ src,
                             __nv_bfloat16* __restrict__ hi,
                             __nv_bfloat16* __restrict__ lo, int n4) {
    int i = blockIdx.x * 256 + threadIdx.x;
    if (i >= n4) return;
    float4 v = src[i];
    split2(v.x, v.y, hi + i*4,     lo + i*4);
    split2(v.z, v.w, hi + i*4 + 2, lo + i*4 + 2);
}

// ---------------- per-layer mega split: QKV | Wo | W1 | W2 | rel + bias concat ----------------
__global__ void megasplit_kernel(
    const float4* __restrict__ wq, const float4* __restrict__ wk,
    const float4* __restrict__ wv, const float4* __restrict__ wo,
    const float4* __restrict__ w1, const float4* __restrict__ w2,
    const float4* __restrict__ rl,
    const float4* __restrict__ ba, const float4* __restrict__ bb,
    const float4* __restrict__ bc, float4* __restrict__ bias3,
    __nv_bfloat16* __restrict__ hi, __nv_bfloat16* __restrict__ lo,
    int s, int relq)
{
    int i = blockIdx.x * 256 + threadIdx.x;
    int nsplit = 12*s + relq;
    if (i >= nsplit) {
        int t = i - nsplit;           // bias concat: 3*ND/4 = 768 float4
        if (t < 3*ND/4) {
            const float4* src = (t < ND/4) ? ba : (t < ND/2 ? bb : bc);
            int j = (t < ND/4) ? t : (t < ND/2 ? t - ND/4 : t - ND/2);
            bias3[t] = src[j];
        }
        return;
    }
    const float4* src;
    int j;
    if (i < 3*s) {
        if (i < s)        { src = wq; j = i; }
        else if (i < 2*s) { src = wk; j = i - s; }
        else              { src = wv; j = i - 2*s; }
    } else if (i < 4*s)   { src = wo; j = i - 3*s; }
    else if (i < 8*s)     { src = w1; j = i - 4*s; }
    else if (i < 12*s)    { src = w2; j = i - 8*s; }
    else                  { src = rl; j = i - 12*s; }
    float4 v = src[j];
    split2(v.x, v.y, hi + (size_t)i*4,     lo + (size_t)i*4);
    split2(v.z, v.w, hi + (size_t)i*4 + 2, lo + (size_t)i*4 + 2);
}

// ---------------- embedding: x = emb[tgt]*32, also emit hi/lo ----------------
__global__ void embed_kernel(const int* __restrict__ tgt,
                             const float* __restrict__ emb,
                             float* __restrict__ x,
                             __nv_bfloat16* __restrict__ xh,
                             __nv_bfloat16* __restrict__ xl) {
    int idx = blockIdx.x * blockDim.x + threadIdx.x;
    int row = idx >> 8;
    int c4  = idx & 255;
    float4 v = reinterpret_cast<const float4*>(emb + (size_t)tgt[row] * ND)[c4];
    v.x *= 32.f; v.y *= 32.f; v.z *= 32.f; v.w *= 32.f;
    reinterpret_cast<float4*>(x)[idx] = v;
    split2(v.x, v.y, xh + idx*4,     xl + idx*4);
    split2(v.z, v.w, xh + idx*4 + 2, xl + idx*4 + 2);
}

// ---------------- fused split-K reduce + residual + LayerNorm ----------------
__global__ __launch_bounds__(256) void red_ln_kernel(
    float* __restrict__ x, __nv_bfloat16* __restrict__ xh, __nv_bfloat16* __restrict__ xl,
    const float* __restrict__ P, const float* __restrict__ bias,
    const float* __restrict__ gw, const float* __restrict__ bw)
{
    __shared__ float buf[ND];
    __shared__ float red[33];
    int row = blockIdx.x;
    int tid = threadIdx.x;
    size_t base = (size_t)row * ND;
    const float* P0 = P + base;
    const float* P1 = P + (size_t)NROWS*ND + base;

    float s = 0.f;
    for (int d = tid; d < ND; d += 256) {
        float t = x[base + d] + P0[d] + P1[d] + bias[d];
        buf[d] = t;
        s += t;
    }
    #pragma unroll
    for (int off = 16; off; off >>= 1) s += __shfl_xor_sync(0xffffffffu, s, off);
    if ((tid & 31) == 0) red[tid >> 5] = s;
    __syncthreads();
    if (tid < 32) {
        float v2 = (tid < 8) ? red[tid] : 0.f;
        #pragma unroll
        for (int off = 4; off; off >>= 1) v2 += __shfl_xor_sync(0xffffffffu, v2, off);
        if (tid == 0) red[32] = v2;
    }
    __syncthreads();
    float mean = red[32] * (1.f/ND);

    float sv = 0.f;
    for (int d = tid; d < ND; d += 256) {
        float t = buf[d] - mean;
        sv += t*t;
    }
    #pragma unroll
    for (int off = 16; off; off >>= 1) sv += __shfl_xor_sync(0xffffffffu, sv, off);
    __syncthreads();
    if ((tid & 31) == 0) red[tid >> 5] = sv;
    __syncthreads();
    if (tid < 32) {
        float v2 = (tid < 8) ? red[tid] : 0.f;
        #pragma unroll
        for (int off = 4; off; off >>= 1) v2 += __shfl_xor_sync(0xffffffffu, v2, off);
        if (tid == 0) red[32] = v2;
    }
    __syncthreads();
    float inv = rsqrtf(red[32] * (1.f/ND) + 1e-5f);
    for (int d = tid*2; d < ND; d += 512) {
        float v0 = (buf[d]   - mean) * inv * gw[d]   + bw[d];
        float v1 = (buf[d+1] - mean) * inv * gw[d+1] + bw[d+1];
        x[base + d]   = v0;
        x[base + d+1] = v1;
        split2(v0, v1, xh + base + d, xl + base + d);
    }
}

// ---------------- split-bf16 tensor-core GEMM (mma.sync) ----------------
#define STG 32768
#define TOFF 8192
#define GEMM_SMEM (3*STG)

__device__ __forceinline__ void ld_tile_async(
    uint32_t sbase, const __nv_bfloat16* __restrict__ g,
    int ldk, int row0, int k0, int rmax, int tid)
{
    #pragma unroll
    for (int it = 0; it < 2; it++) {
        int qq = tid + it * 256;
        int r = qq >> 2, c = qq & 3;
        uint32_t dst = sbase + r * 64 + ((c ^ ((r >> 1) & 3)) << 4);
        int rr = (r < rmax) ? r : 0;
        const __nv_bfloat16* src = g + (size_t)(row0 + rr) * ldk + k0 + c * 8;
        int sz = (r < rmax) ? 16 : 0;
        CP_ASYNC16(dst, src, sz);
    }
}

__device__ __forceinline__ void ld_stage(
    uint32_t sbase, const __nv_bfloat16* Ah, const __nv_bfloat16* Al,
    const __nv_bfloat16* Bh, const __nv_bfloat16* Bl,
    int ldk, int m0, int n0, int k0, int bn, int tid, int terms)
{
    ld_tile_async(sbase + 0*TOFF, Ah, ldk, m0, k0, 128, tid);
    ld_tile_async(sbase + 2*TOFF, Bh, ldk, n0, k0, bn, tid);
    if (terms == 3) {
        ld_tile_async(sbase + 1*TOFF, Al, ldk, m0, k0, 128, tid);
        ld_tile_async(sbase + 3*TOFF, Bl, ldk, n0, k0, bn, tid);
    }
}

__global__ __launch_bounds__(256, 2) void gemm_tc(
    float* __restrict__ C, __nv_bfloat16* __restrict__ Ch, __nv_bfloat16* __restrict__ Cl,
    const __nv_bfloat16* __restrict__ Ah, const __nv_bfloat16* __restrict__ Al,
    const __nv_bfloat16* __restrict__ Bh, const __nv_bfloat16* __restrict__ Bl,
    const float* __restrict__ bias, int M, int N, int Nh, int K, int ldk,
    float alpha, int relu, int terms, int tri)
{
    extern __shared__ char sm[];
    uint32_t smb = smem_u32(sm);
    int tid = threadIdx.x;
    int wid = tid >> 5;
    int lane = tid & 31;
    int wm = wid & 1;
    int wn = wid >> 1;
    int m0 = blockIdx.y * 128;
    int n0 = blockIdx.x * 128;

    // triangular skip (QR): rows m0..m0+127 encode i = (row>>4) mod 1024;
    // column block dead iff n0+127 < 1016 - i_min.
    if (tri) {
        int imin = (m0 >> 4) & (NS - 1);
        if (n0 + 127 < 1016 - imin) return;
    }

    int kbase = blockIdx.z * K;
    if (C) C += (size_t)blockIdx.z * M * N;
    int NT = K >> 5;
    int bn = N - n0; if (bn > 128) bn = 128;

    ld_stage(smb, Ah, Al, Bh, Bl, ldk, m0, n0, kbase, bn, tid, terms);
    CP_COMMIT();
    if (NT > 1) {
        ld_stage(smb + STG, Ah, Al, Bh, Bl, ldk, m0, n0, kbase + 32, bn, tid, terms);
        CP_COMMIT();
    }

    float acc[4][4][4];
    #pragma unroll
    for (int i = 0; i < 4; i++)
        #pragma unroll
        for (int j = 0; j < 4; j++)
            #pragma unroll
            for (int e = 0; e < 4; e++) acc[i][j][e] = 0.f;

    int slot = 0, pslot = 2;
    for (int kt = 0; kt < NT; kt++) {
        if (kt + 1 < NT) { CP_WAIT1(); } else { CP_WAIT0(); }
        __syncthreads();

        if (kt + 2 < NT) {
            ld_stage(smb + pslot * STG, Ah, Al, Bh, Bl, ldk, m0, n0,
                     kbase + ((kt + 2) << 5), bn, tid, terms);
            CP_COMMIT();
        }

        uint32_t sA = smb + slot * STG;
        uint32_t sB = sA + 2*TOFF;

        #pragma unroll
        for (int ks = 0; ks < 2; ks++) {
            uint32_t ah[4][4], al[4][4], bh[4][2], bl[4][2];
            #pragma unroll
            for (int mf = 0; mf < 4; mf++) {
                int row = wm * 64 + mf * 16 + (lane & 15);
                int cc = ks * 2 + (lane >> 4);
                uint32_t ad = sA + row * 64 + (((cc ^ ((row >> 1) & 3))) << 4);
                LDSM4(ah[mf], ad);
                if (terms == 3) LDSM4(al[mf], ad + TOFF);
            }
            #pragma unroll
            for (int nf = 0; nf < 4; nf++) {
                int rn = wn * 32 + nf * 8 + (lane & 7);
                int cc = ks * 2 + ((lane >> 3) & 1);
                uint32_t bd = sB + rn * 64 + (((cc ^ ((rn >> 1) & 3))) << 4);
                LDSM2(bh[nf], bd);
                if (terms == 3) LDSM2(bl[nf], bd + TOFF);
            }
            #pragma unroll
            for (int mf = 0; mf < 4; mf++)
                #pragma unroll
                for (int nf = 0; nf < 4; nf++)
                    MMA16816(acc[mf][nf], ah[mf], bh[nf]);
            if (terms == 3) {
                #pragma unroll
                for (int mf = 0; mf < 4; mf++)
                    #pragma unroll
                    for (int nf = 0; nf < 4; nf++)
                        MMA16816(acc[mf][nf], ah[mf], bl[nf]);
                #pragma unroll
                for (int mf = 0; mf < 4; mf++)
                    #pragma unroll
                    for (int nf = 0; nf < 4; nf++)
                        MMA16816(acc[mf][nf], al[mf], bh[nf]);
            }
        }
        slot = (slot == 2) ? 0 : slot + 1;
        pslot = (pslot == 2) ? 0 : pslot + 1;
    }

    // epilogue: vector paths require even row strides (alignment!)
    bool fastC  = (C != nullptr)  && ((N & 1) == 0)  && (n0 + 128 <= N);
    bool fastCh = (Ch != nullptr) && ((Nh & 1) == 0) && (n0 + 128 <= Nh);
    #pragma unroll
    for (int mf = 0; mf < 4; mf++) {
        int r0 = m0 + wm * 64 + mf * 16 + (lane >> 2);
        #pragma unroll
        for (int half = 0; half < 2; half++) {
            int row = r0 + half * 8;
            size_t rbase = (size_t)row * N;
            size_t rbh   = (size_t)row * Nh;
            #pragma unroll
            for (int nf = 0; nf < 4; nf++) {
                int col = n0 + wn * 32 + nf * 8 + (lane & 3) * 2;
                float v0 = acc[mf][nf][half * 2 + 0];
                float v1 = acc[mf][nf][half * 2 + 1];
                if (bias) { v0 += bias[col]; v1 += __ldg(&bias[col + 1]); }
                v0 *= alpha; v1 *= alpha;
                if (relu) { v0 = fmaxf(v0, 0.f); v1 = fmaxf(v1, 0.f); }
                if (fastC) {
                    *reinterpret_cast<float2*>(C + rbase + col) = make_float2(v0, v1);
                } else if (C) {
                    if (col < N)     C[rbase + col] = v0;
                    if (col + 1 < N) C[rbase + col + 1] = v1;
                }
                if (fastCh) {
                    if (Cl) split2(v0, v1, Ch + rbh + col, Cl + rbh + col);
                    else *reinterpret_cast<__nv_bfloat162*>(Ch + rbh + col) =
                             __nv_bfloat162(__float2bfloat16(v0), __float2bfloat16(v1));
                } else if (Ch) {
                    if (col < Nh)     Ch[rbh + col] = __float2bfloat16(v0);
                    if (col + 1 < Nh) Ch[rbh + col + 1] = __float2bfloat16(v1);
                }
            }
        }
    }
}

// ---------------- fused attention, split-KV=8 (flash partials) ----------------
#define QT 128
#define KT 64
#define LDQ 68
#define QKVS (3*ND)

__global__ __launch_bounds__(128, 2) void attn_kernel(
    float* __restrict__ po, float* __restrict__ pm, float* __restrict__ pl,
    const float* __restrict__ qkv, const __nv_bfloat16* __restrict__ qrb,
    const int* __restrict__ tgt)
{
    extern __shared__ float smf[];
    float* qs = smf;
    float* ks = qs + QT*LDQ;
    float* vs = ks + KT*LDQ;
    float* ps = vs + KT*LDQ;
    int*   pf = (int*)(ps + QT*LDQ);

    int split = blockIdx.y;
    int bh = blockIdx.z;
    int b = bh >> 4, h = bh & 15;
    int tid = threadIdx.x;
    int i0 = blockIdx.x * QT;
    int i  = i0 + tid;

    int jend = (tgt[b*NS] == 0) ? NS : (i0 + QT);
    int jstart = split * KVSEG;
    int jstop  = (jend < (split + 1) * KVSEG) ? jend : (split + 1) * KVSEG;

    size_t rh = (size_t)(b*NS + i)*NH + h + (size_t)split*NROWS*NH;

    if (jstart >= jstop) {
        pm[rh] = -1e30f;
        pl[rh] = 0.f;
        return;
    }

    float o[NDH];
    #pragma unroll
    for (int d = 0; d < NDH; d++) o[d] = 0.f;
    float m = -1e30f, l = 0.f;

    for (int t = tid; t < QT*NDH/4; t += 128) {
        int r  = t >> 4;
        int c4 = (t & 15) << 2;
        float4 va = *reinterpret_cast<const float4*>(
            &qkv[((size_t)(b*NS + i0 + r))*QKVS + h*NDH + c4]);
        va.x *= 0.125f; va.y *= 0.125f; va.z *= 0.125f; va.w *= 0.125f;
        *reinterpret_cast<float4*>(&qs[r*LDQ + c4]) = va;
    }

    const __nv_bfloat16* qrrow =
        qrb + ((size_t)((b*NS + i)*NH + h)) * NRQ + (1023 - i);

    for (int j0 = jstart; j0 < jstop; j0 += KT) {
        __syncthreads();
        for (int t = tid; t < KT*NDH/4; t += 128) {
            int r  = t >> 4;
            int c4 = (t & 15) << 2;
            size_t g = ((size_t)(b*NS + j0 + r))*QKVS + h*NDH + c4;
            *reinterpret_cast<float4*>(&ks[r*LDQ + c4]) =
                *reinterpret_cast<const float4*>(&qkv[g + ND]);
            *reinterpret_cast<float4*>(&vs[r*LDQ + c4]) =
                *reinterpret_cast<const float4*>(&qkv[g + 2*ND]);
        }
        if (tid < KT) pf[tid] = (tgt[b*NS + j0 + tid] == 0) ? 1 : 0;
        __syncthreads();

        float s[KT];
        #pragma unroll
        for (int j = 0; j < KT; j++) s[j] = 0.f;
        #pragma unroll 1
        for (int d = 0; d < NDH; d += 4) {
            float4 qd = *reinterpret_cast<const float4*>(&qs[tid*LDQ + d]);
            #pragma unroll
            for (int j = 0; j < KT; j++) {
                float4 kj = *reinterpret_cast<const float4*>(&ks[j*LDQ + d]);
                s[j] += qd.x*kj.x + qd.y*kj.y + qd.z*kj.z + qd.w*kj.w;
            }
        }
        float mt = m;
        #pragma unroll
        for (int j = 0; j < KT; j++) {
            int jj = j0 + j;
            float val;
            if (jj > i || pf[j]) val = -1e9f;
            else val = s[j] + __bfloat162float(qrrow[jj]);
            s[j] = val;
            mt = fmaxf(mt, val);
        }
        float corr = __expf(m - mt);
        m = mt;
        l *= corr;
        #pragma unroll
        for (int d = 0; d < NDH; d++) o[d] *= corr;
        #pragma unroll
        for (int j = 0; j < KT; j += 4) {
            float4 pv;
            pv.x = __expf(s[j]   - m);
            pv.y = __expf(s[j+1] - m);
            pv.z = __expf(s[j+2] - m);
            pv.w = __expf(s[j+3] - m);
            l += pv.x + pv.y + pv.z + pv.w;
            *reinterpret_cast<float4*>(&ps[tid*LDQ + j]) = pv;
        }
        #pragma unroll 1
        for (int j = 0; j < KT; j++) {
            float p = ps[tid*LDQ + j];
            #pragma unroll
            for (int d = 0; d < NDH; d += 4) {
                float4 vj = *reinterpret_cast<const float4*>(&vs[j*LDQ + d]);
                o[d]   += p*vj.x;
                o[d+1] += p*vj.y;
                o[d+2] += p*vj.z;
                o[d+3] += p*vj.w;
            }
        }
    }

    pm[rh] = m;
    pl[rh] = l;
    size_t ob = (size_t)split*NROWS*ND + ((size_t)(b*NS + i))*ND + h*NDH;
    #pragma unroll
    for (int d = 0; d < NDH; d += 4)
        *reinterpret_cast<float4*>(&po[ob + d]) = make_float4(o[d], o[d+1], o[d+2], o[d+3]);
}

// ---------------- attention combine: merge NSPLIT partials -> bf16 hi/lo ----------------
__global__ __launch_bounds__(256) void attn_combine(
    __nv_bfloat16* __restrict__ oh, __nv_bfloat16* __restrict__ ol,
    const float* __restrict__ po, const float* __restrict__ pm, const float* __restrict__ pl)
{
    int row = blockIdx.x;
    int tid = threadIdx.x;
    for (int e = tid*2; e < ND; e += 512) {
        int h = e >> 6;
        size_t rh = (size_t)row*NH + h;
        float ms[NSPLIT], ls[NSPLIT];
        float m = -1e30f;
        #pragma unroll
        for (int s = 0; s < NSPLIT; s++) {
            ms[s] = pm[(size_t)s*NROWS*NH + rh];
            ls[s] = pl[(size_t)s*NROWS*NH + rh];
            m = fmaxf(m, ms[s]);
        }
        float denom = 0.f;
        float w[NSPLIT];
        #pragma unroll
        for (int s = 0; s < NSPLIT; s++) {
            w[s] = __expf(ms[s] - m);
            denom += w[s] * ls[s];
        }
        float inv = 1.f / denom;
        size_t b0 = (size_t)row*ND + e;
        float v0 = 0.f, v1 = 0.f;
        #pragma unroll
        for (int s = 0; s < NSPLIT; s++) {
            if (w[s] > 0.f) {
                size_t sb = (size_t)s*NROWS*ND + b0;
                v0 += w[s] * po[sb];
                v1 += w[s] * po[sb + 1];
            }
        }
        v0 *= inv; v1 *= inv;
        split2(v0, v1, oh + b0, ol + b0);
    }
}

// ---------------- host orchestration ----------------
extern "C" void kernel_launch(void* const* d_in, const int* in_sizes, int n_in,
                              void* d_out, int out_size)
{
    (void)in_sizes; (void)n_in; (void)out_size;
    const int*   tgt = (const int*)d_in[0];
    const float* emb = (const float*)d_in[1];
    const float* Wq  = (const float*)d_in[2];
    const float* bq  = (const float*)d_in[3];
    const float* Wk  = (const float*)d_in[4];
    const float* bk  = (const float*)d_in[5];
    const float* Wv  = (const float*)d_in[6];
    const float* bv  = (const float*)d_in[7];
    const float* Wo  = (const float*)d_in[8];
    const float* bo  = (const float*)d_in[9];
    const float* rel = (const float*)d_in[10];
    const float* W1  = (const float*)d_in[11];
    const float* b1  = (const float*)d_in[12];
    const float* W2  = (const float*)d_in[13];
    const float* b2  = (const float*)d_in[14];
    const float* g1  = (const float*)d_in[15];
    const float* be1 = (const float*)d_in[16];
    const float* g2  = (const float*)d_in[17];
    const float* be2 = (const float*)d_in[18];
    const float* Wf  = (const float*)d_in[19];
    const float* bf  = (const float*)d_in[20];
    float* logits = (float*)d_out;

    float *x_, *qkv_, *p_, *bias3_, *po_, *pm_, *pl_;
    __nv_bfloat16 *qrb, *xh, *xl, *qh, *ql, *oh, *ol, *hh, *hl, *Bh, *Bl, *Wfh, *Wfl;
    cudaGetSymbolAddress((void**)&x_,    g_x);
    cudaGetSymbolAddress((void**)&qkv_,  g_qkv);
    cudaGetSymbolAddress((void**)&p_,    g_p);
    cudaGetSymbolAddress((void**)&bias3_, g_bias3);
    cudaGetSymbolAddress((void**)&po_,  g_po);
    cudaGetSymbolAddress((void**)&pm_,  g_pm);
    cudaGetSymbolAddress((void**)&pl_,  g_pl);
    cudaGetSymbolAddress((void**)&qrb, g_qrb);
    cudaGetSymbolAddress((void**)&xh,  g_xh);
    cudaGetSymbolAddress((void**)&xl,  g_xl);
    cudaGetSymbolAddress((void**)&qh,  g_qh);
    cudaGetSymbolAddress((void**)&ql,  g_ql);
    cudaGetSymbolAddress((void**)&oh,  g_oh);
    cudaGetSymbolAddress((void**)&ol,  g_ol);
    cudaGetSymbolAddress((void**)&hh,  g_hh);
    cudaGetSymbolAddress((void**)&hl,  g_hl);
    cudaGetSymbolAddress((void**)&Bh,  g_Bh);
    cudaGetSymbolAddress((void**)&Bl,  g_Bl);
    cudaGetSymbolAddress((void**)&Wfh, g_Wfh);
    cudaGetSymbolAddress((void**)&Wfl, g_Wfl);

    int attn_smem = (QT*LDQ + KT*LDQ + KT*LDQ + QT*LDQ)*(int)sizeof(float) + KT*(int)sizeof(int);
    cudaFuncSetAttribute(attn_kernel, cudaFuncAttributeMaxDynamicSharedMemorySize, attn_smem);
    cudaFuncSetAttribute(gemm_tc, cudaFuncAttributeMaxDynamicSharedMemorySize, GEMM_SMEM);

    // side stream + events for overlapped weight splitting (fork-join capture)
    cudaStream_t s2;
    cudaStreamCreateWithFlags(&s2, cudaStreamNonBlocking);
    cudaEvent_t eStart, eWf, eSp[NL], eDone[2];
    cudaEventCreateWithFlags(&eStart, cudaEventDisableTiming);
    cudaEventCreateWithFlags(&eWf, cudaEventDisableTiming);
    for (int i = 0; i < NL; i++) cudaEventCreateWithFlags(&eSp[i], cudaEventDisableTiming);
    for (int i = 0; i < 2;  i++) cudaEventCreateWithFlags(&eDone[i], cudaEventDisableTiming);

    __nv_bfloat16* nb = nullptr;
    float* nf = nullptr;
    const int s4 = WDDE/4;
    const int relq = NRQ*NDH/4;
    const int mgrid = (12*s4 + relq + 3*ND/4 + 255)/256;
    const size_t WDD = (size_t)WDDE;

    auto launch_megasplit = [&](int l, cudaStream_t st) {
        size_t base = (size_t)(l & 1) * LOFF;
        megasplit_kernel<<<mgrid, 256, 0, st>>>(
            reinterpret_cast<const float4*>(Wq + l*WDD),
            reinterpret_cast<const float4*>(Wk + l*WDD),
            reinterpret_cast<const float4*>(Wv + l*WDD),
            reinterpret_cast<const float4*>(Wo + l*WDD),
            reinterpret_cast<const float4*>(W1 + (size_t)l*NDFF*ND),
            reinterpret_cast<const float4*>(W2 + (size_t)l*ND*NDFF),
            reinterpret_cast<const float4*>(rel + (size_t)l*(2*NS-1)*NDH),
            reinterpret_cast<const float4*>(bq + l*ND),
            reinterpret_cast<const float4*>(bk + l*ND),
            reinterpret_cast<const float4*>(bv + l*ND),
            reinterpret_cast<float4*>(bias3_ + (l & 1)*3*ND),
            Bh + base, Bl + base, s4, relq);
    };

    embed_kernel<<<NROWS*ND/4/256, 256>>>(tgt, emb, x_, xh, xl);
    cudaEventRecord(eStart, 0);

    // fork: splits for layers 0,1 and Wf run on s2 up front
    cudaStreamWaitEvent(s2, eStart, 0);
    launch_megasplit(0, s2);
    cudaEventRecord(eSp[0], s2);
    launch_megasplit(1, s2);
    cudaEventRecord(eSp[1], s2);
    split_kernel<<<(int)((size_t)NV*ND/4 + 255)/256, 256, 0, s2>>>(
        reinterpret_cast<const float4*>(Wf), Wfh, Wfl, (int)((size_t)NV*ND/4));
    cudaEventRecord(eWf, s2);

    for (int l = 0; l < NL; l++) {
        size_t base = (size_t)(l & 1) * LOFF;
        float* bias3l = bias3_ + (l & 1)*3*ND;

        cudaStreamWaitEvent(0, eSp[l], 0);

        // fused QKV projection: N=3072, grid (24,16)
        gemm_tc<<<dim3(3*ND/128, NROWS/128), 256, GEMM_SMEM>>>(
            qkv_, qh, ql, xh, xl, Bh + base, Bl + base, bias3l,
            NROWS, 3*ND, ND, ND, ND, 1.f, 0, 3, 0);

        // QR: 1024 rel columns, triangular CTA skip, single-term bf16, hi-only
        gemm_tc<<<dim3(NRQ/128, NROWS*NH/128), 256, GEMM_SMEM>>>(
            nf, qrb, nb, qh, ql, Bh + base + 12*WDD, Bl + base + 12*WDD, nf,
            NROWS*NH, NRQ, NRQ, NDH, NDH, 0.125f, 0, 1, 1);

        // attention: split-KV=8, then combine
        attn_kernel<<<dim3(NS/QT, NSPLIT, NB*NH), 128, attn_smem>>>(
            po_, pm_, pl_, qkv_, qrb, tgt);
        attn_combine<<<NROWS, 256>>>(oh, ol, po_, pm_, pl_);

        // output projection (split-K=2) + fused reduce+LN
        gemm_tc<<<dim3(ND/128, NROWS/128, 2), 256, GEMM_SMEM>>>(
            p_, nb, nb, oh, ol, Bh + base + 3*WDD, Bl + base + 3*WDD, nf,
            NROWS, ND, ND, 512, ND, 1.f, 0, 3, 0);
        red_ln_kernel<<<NROWS, 256>>>(x_, xh, xl, p_, bo + l*ND, g1 + l*ND, be1 + l*ND);

        // FFN1: write h directly as bf16 hi/lo
        gemm_tc<<<dim3(NDFF/128, NROWS/128), 256, GEMM_SMEM>>>(
            nf, hh, hl, xh, xl, Bh + base + 4*WDD, Bl + base + 4*WDD, b1 + l*NDFF,
            NROWS, NDFF, NDFF, ND, ND, 1.f, 1, 3, 0);
        // FFN2 (split-K=2): last reader of this layer's weight buffer
        gemm_tc<<<dim3(ND/128, NROWS/128, 2), 256, GEMM_SMEM>>>(
            p_, nb, nb, hh, hl, Bh + base + 8*WDD, Bl + base + 8*WDD, nf,
            NROWS, ND, ND, 2048, NDFF, 1.f, 0, 3, 0);

        // buffer (l&1) is now free after FFN2 -> schedule split for layer l+2
        if (l < NL - 2) {
            cudaEventRecord(eDone[l], 0);
            cudaStreamWaitEvent(s2, eDone[l], 0);
            launch_megasplit(l + 2, s2);
            cudaEventRecord(eSp[l + 2], s2);
        }

        red_ln_kernel<<<NROWS, 256>>>(x_, xh, xl, p_, b2 + l*ND, g2 + l*ND, be2 + l*ND);
    }

    // final logits: M=2048, N=32000, K=1024 (join Wf split branch)
    cudaStreamWaitEvent(0, eWf, 0);
    gemm_tc<<<dim3(NV/128, NROWS/128), 256, GEMM_SMEM>>>(
        logits, nb, nb, xh, xl, Wfh, Wfl, bf, NROWS, NV, NV, ND, ND, 1.f, 0, 3, 0);
}